// round 1
// baseline (speedup 1.0000x reference)
#include <cuda_runtime.h>

// ---------------- problem constants ----------------
#define NNODES 20000
#define FIN    64
#define HDIM   512
#define NTYPES 5
#define TEDGE  6
#define NEDGE  160000
#define NH     (NNODES * HDIM)          // 10,240,000 floats per (type) feature plane

// EDGE_TYPES = ((4,1),(1,0),(0,2),(2,3),(3,0),(1,4))
__constant__ int c_srcT[TEDGE] = {4, 1, 0, 2, 3, 1};
__constant__ int c_dstT[TEDGE] = {1, 0, 2, 3, 0, 4};

// ---------------- device scratch (no allocs allowed) ----------------
__device__ float g_hA[NTYPES * NH];     // 204.8 MB
__device__ float g_hB[NTYPES * NH];     // 204.8 MB
__device__ float g_agg6[TEDGE * NH];    // 245.8 MB
__device__ float g_tmp6[TEDGE * NH];    // 245.8 MB

// ---------------- batched SGEMM ----------------
// C[z] = op( A[z] (MxK, row-major) @ B[z] (KxN, row-major) + bias[z] )
// per-z offsets/flags come in by value.
#define F_RELU  1
#define F_ACCUM 2

struct GemmMap {
    long long aoff[TEDGE];
    long long boff[TEDGE];
    long long biasoff[TEDGE];
    long long coff[TEDGE];
    int       flags[TEDGE];
};

__global__ __launch_bounds__(256, 2)
void sgemm_kernel(const float* __restrict__ Ab, const float* __restrict__ Bb,
                  const float* __restrict__ biasb, float* __restrict__ Cb,
                  int M, int N, int K, GemmMap map)
{
    const int z = blockIdx.z;
    const float* __restrict__ A    = Ab    + map.aoff[z];
    const float* __restrict__ B    = Bb    + map.boff[z];
    const float* __restrict__ bias = biasb + map.biasoff[z];
    float* __restrict__       C    = Cb    + map.coff[z];
    const int flags = map.flags[z];

    __shared__ float As[16][128];   // transposed A tile: As[k][m]
    __shared__ float Bs[16][128];   // Bs[k][n]

    const int tid = threadIdx.x;
    const int tx  = tid & 15;       // 16 cols of threads
    const int ty  = tid >> 4;       // 16 rows of threads
    const int bm  = blockIdx.y << 7;
    const int bn  = blockIdx.x << 7;

    float acc[8][8];
#pragma unroll
    for (int i = 0; i < 8; i++)
#pragma unroll
        for (int j = 0; j < 8; j++) acc[i][j] = 0.f;

    float4 aR[2], bR[2];
    const int nk = K >> 4;

    // ---- initial tile load (kt = 0) ----
#pragma unroll
    for (int i = 0; i < 2; i++) {
        int id = tid + (i << 8);
        int r = id >> 2, kq = id & 3;
        int gr = bm + r;
        if (gr < M) aR[i] = *(const float4*)(A + (long long)gr * K + (kq << 2));
        else        aR[i] = make_float4(0.f, 0.f, 0.f, 0.f);
        int kr = id >> 5, cq = id & 31;
        bR[i] = *(const float4*)(B + (long long)kr * N + bn + (cq << 2));
    }
#pragma unroll
    for (int i = 0; i < 2; i++) {
        int id = tid + (i << 8);
        int r = id >> 2, kq = (id & 3) << 2;
        As[kq + 0][r] = aR[i].x;
        As[kq + 1][r] = aR[i].y;
        As[kq + 2][r] = aR[i].z;
        As[kq + 3][r] = aR[i].w;
        int kr = id >> 5, cq = id & 31;
        *(float4*)&Bs[kr][cq << 2] = bR[i];
    }
    __syncthreads();

    for (int kt = 0; kt < nk; kt++) {
        // prefetch next tile to registers
        if (kt + 1 < nk) {
            const float* An = A + ((kt + 1) << 4);
            const float* Bn = B + (long long)((kt + 1) << 4) * N;
#pragma unroll
            for (int i = 0; i < 2; i++) {
                int id = tid + (i << 8);
                int r = id >> 2, kq = id & 3;
                int gr = bm + r;
                if (gr < M) aR[i] = *(const float4*)(An + (long long)gr * K + (kq << 2));
                else        aR[i] = make_float4(0.f, 0.f, 0.f, 0.f);
                int kr = id >> 5, cq = id & 31;
                bR[i] = *(const float4*)(Bn + (long long)kr * N + bn + (cq << 2));
            }
        }

#pragma unroll
        for (int k = 0; k < 16; k++) {
            float4 a0 = *(const float4*)&As[k][ty << 2];
            float4 a1 = *(const float4*)&As[k][64 + (ty << 2)];
            float4 b0 = *(const float4*)&Bs[k][tx << 2];
            float4 b1 = *(const float4*)&Bs[k][64 + (tx << 2)];
            float av[8] = {a0.x, a0.y, a0.z, a0.w, a1.x, a1.y, a1.z, a1.w};
            float bv[8] = {b0.x, b0.y, b0.z, b0.w, b1.x, b1.y, b1.z, b1.w};
#pragma unroll
            for (int ii = 0; ii < 8; ii++)
#pragma unroll
                for (int jj = 0; jj < 8; jj++)
                    acc[ii][jj] = fmaf(av[ii], bv[jj], acc[ii][jj]);
        }
        __syncthreads();

        if (kt + 1 < nk) {
#pragma unroll
            for (int i = 0; i < 2; i++) {
                int id = tid + (i << 8);
                int r = id >> 2, kq = (id & 3) << 2;
                As[kq + 0][r] = aR[i].x;
                As[kq + 1][r] = aR[i].y;
                As[kq + 2][r] = aR[i].z;
                As[kq + 3][r] = aR[i].w;
                int kr = id >> 5, cq = id & 31;
                *(float4*)&Bs[kr][cq << 2] = bR[i];
            }
            __syncthreads();
        }
    }

    // ---- epilogue: bias + (accum) + (relu), float4 stores ----
    float4 bia0 = *(const float4*)(bias + bn + (tx << 2));
    float4 bia1 = *(const float4*)(bias + bn + 64 + (tx << 2));

#pragma unroll
    for (int ih = 0; ih < 2; ih++) {
#pragma unroll
        for (int ii = 0; ii < 4; ii++) {
            int r = bm + (ih << 6) + (ty << 2) + ii;
            if (r >= M) continue;
#pragma unroll
            for (int jh = 0; jh < 2; jh++) {
                int col = bn + (jh << 6) + (tx << 2);
                float4 bb = jh ? bia1 : bia0;
                float4 v;
                v.x = acc[(ih << 2) + ii][(jh << 2) + 0] + bb.x;
                v.y = acc[(ih << 2) + ii][(jh << 2) + 1] + bb.y;
                v.z = acc[(ih << 2) + ii][(jh << 2) + 2] + bb.z;
                v.w = acc[(ih << 2) + ii][(jh << 2) + 3] + bb.w;
                float* cp = C + (long long)r * N + col;
                if (flags & F_ACCUM) {
                    float4 o = *(const float4*)cp;
                    v.x += o.x; v.y += o.y; v.z += o.z; v.w += o.w;
                }
                if (flags & F_RELU) {
                    v.x = fmaxf(v.x, 0.f); v.y = fmaxf(v.y, 0.f);
                    v.z = fmaxf(v.z, 0.f); v.w = fmaxf(v.w, 0.f);
                }
                *(float4*)cp = v;
            }
        }
    }
}

// ---------------- scatter: agg6[t][dst] += h[srcT[t]][src], one warp per edge ----------------
__global__ void scatter_kernel(const float* __restrict__ h, float* __restrict__ agg6,
                               const int* __restrict__ edges /* [6][2][NEDGE] */)
{
    int gw   = (blockIdx.x * blockDim.x + threadIdx.x) >> 5;
    int lane = threadIdx.x & 31;
    if (gw >= TEDGE * NEDGE) return;
    int t = gw / NEDGE;
    int e = gw - t * NEDGE;
    const int* src = edges + (long long)t * 2 * NEDGE;
    const int* dst = src + NEDGE;
    int sn = __ldg(src + e);
    int dn = __ldg(dst + e);
    int st = c_srcT[t];

    const float4* srow = (const float4*)(h + ((long long)st * NNODES + sn) * HDIM);
    float* arow = agg6 + ((long long)t * NNODES + dn) * HDIM;
#pragma unroll
    for (int k = 0; k < 4; k++) {
        float4 v = __ldg(srow + lane + (k << 5));
        int c = (lane + (k << 5)) << 2;
        atomicAdd(arow + c + 0, v.x);
        atomicAdd(arow + c + 1, v.y);
        atomicAdd(arow + c + 2, v.z);
        atomicAdd(arow + c + 3, v.w);
    }
}

// ---------------- output head: out = h[0] @ W_out + b_out, one warp per node ----------------
__global__ void head_kernel(const float* __restrict__ h0, const float* __restrict__ Wout,
                            const float* __restrict__ bout, float* __restrict__ out)
{
    int node = (blockIdx.x * blockDim.x + threadIdx.x) >> 5;
    int lane = threadIdx.x & 31;
    if (node >= NNODES) return;
    const float4* row = (const float4*)(h0 + (long long)node * HDIM);
    const float4* w4  = (const float4*)Wout;
    float s = 0.f;
#pragma unroll
    for (int k = 0; k < 4; k++) {
        float4 a = row[lane + (k << 5)];
        float4 w = __ldg(w4 + lane + (k << 5));
        s += a.x * w.x + a.y * w.y + a.z * w.z + a.w * w.w;
    }
#pragma unroll
    for (int off = 16; off; off >>= 1) s += __shfl_down_sync(0xffffffffu, s, off);
    if (lane == 0) out[node] = s + bout[0];
}

// ---------------- host launch ----------------
extern "C" void kernel_launch(void* const* d_in, const int* in_sizes, int n_in,
                              void* d_out, int out_size)
{
    const float *x = nullptr, *Win = nullptr, *bin = nullptr;
    const float *W1 = nullptr, *b1 = nullptr, *W2 = nullptr, *b2 = nullptr;
    const float *Wout = nullptr, *bout = nullptr;
    const int* edges = nullptr;

    for (int i = 0; i < n_in; i++) {
        int s = in_sizes[i];
        const void* p = d_in[i];
        switch (s) {
            case 6400000: x    = (const float*)p; break;                 // [5,20000,64]
            case 163840:  Win  = (const float*)p; break;                 // [5,64,512]
            case 2560:    bin  = (const float*)p; break;                 // [5,512]
            case 3145728: if (!W1) W1 = (const float*)p; else W2 = (const float*)p; break; // [2,6,512,512]
            case 6144:    if (!b1) b1 = (const float*)p; else b2 = (const float*)p; break; // [2,6,512]
            case 512:     Wout = (const float*)p; break;                 // [512,1]
            case 1:       bout = (const float*)p; break;                 // [1]
            case 1920000: edges = (const int*)p; break;                  // [6,2,160000]
        }
    }

    float *hA, *hB, *agg6, *tmp6;
    cudaGetSymbolAddress((void**)&hA,   g_hA);
    cudaGetSymbolAddress((void**)&hB,   g_hB);
    cudaGetSymbolAddress((void**)&agg6, g_agg6);
    cudaGetSymbolAddress((void**)&tmp6, g_tmp6);

    const int gy = (NNODES + 127) / 128;   // 157
    const int dstT[TEDGE] = {1, 0, 2, 3, 0, 4};

    // 1) input projection: h = relu(x @ W_in + b_in), batched over 5 types
    {
        GemmMap m = {};
        for (int t = 0; t < NTYPES; t++) {
            m.aoff[t]    = (long long)t * NNODES * FIN;
            m.boff[t]    = (long long)t * FIN * HDIM;
            m.biasoff[t] = (long long)t * HDIM;
            m.coff[t]    = (long long)t * NH;
            m.flags[t]   = F_RELU;
        }
        sgemm_kernel<<<dim3(HDIM / 128, gy, NTYPES), 256>>>(x, Win, bin, hA,
                                                            NNODES, HDIM, FIN, m);
    }

    float* hcur = hA;
    float* hnext = hB;

    for (int l = 0; l < 2; l++) {
        // 2a) agg init: agg6[t] = h[dstT[t]]
        for (int t = 0; t < TEDGE; t++) {
            cudaMemcpyAsync(agg6 + (long long)t * NH, hcur + (long long)dstT[t] * NH,
                            (size_t)NH * sizeof(float), cudaMemcpyDeviceToDevice);
        }
        // 2b) scatter-add over all 6 edge types (one warp per edge)
        {
            int warps = TEDGE * NEDGE;                // 960000
            int blocks = (warps + 7) / 8;             // 8 warps / 256-thread block
            scatter_kernel<<<blocks, 256>>>(hcur, agg6, edges);
        }
        // 2c) GEMM1: tmp6[t] = relu(agg6[t] @ W1[l,t] + b1[l,t]), batched z=6
        {
            GemmMap m = {};
            for (int t = 0; t < TEDGE; t++) {
                m.aoff[t]    = (long long)t * NH;
                m.boff[t]    = ((long long)l * TEDGE + t) * HDIM * HDIM;
                m.biasoff[t] = ((long long)l * TEDGE + t) * HDIM;
                m.coff[t]    = (long long)t * NH;
                m.flags[t]   = F_RELU;
            }
            sgemm_kernel<<<dim3(HDIM / 128, gy, TEDGE), 256>>>(agg6, W1, b1, tmp6,
                                                               NNODES, HDIM, HDIM, m);
        }
        // 2d) GEMM2 group 1: t in {0,1,2,3,5} -> distinct dst types, direct store.
        //     dst 0 (t=1) stays raw (t=4 will accumulate + relu), others get relu.
        {
            GemmMap m = {};
            const int zs[5] = {0, 1, 2, 3, 5};
            for (int zi = 0; zi < 5; zi++) {
                int t = zs[zi];
                m.aoff[zi]    = (long long)t * NH;
                m.boff[zi]    = ((long long)l * TEDGE + t) * HDIM * HDIM;
                m.biasoff[zi] = ((long long)l * TEDGE + t) * HDIM;
                m.coff[zi]    = (long long)dstT[t] * NH;
                m.flags[zi]   = (t == 1) ? 0 : F_RELU;
            }
            sgemm_kernel<<<dim3(HDIM / 128, gy, 5), 256>>>(tmp6, W2, b2, hnext,
                                                           NNODES, HDIM, HDIM, m);
        }
        // 2e) GEMM2 group 2: t=4 accumulates into dst 0, then relu.
        {
            GemmMap m = {};
            m.aoff[0]    = (long long)4 * NH;
            m.boff[0]    = ((long long)l * TEDGE + 4) * HDIM * HDIM;
            m.biasoff[0] = ((long long)l * TEDGE + 4) * HDIM;
            m.coff[0]    = 0;                         // dst type 0
            m.flags[0]   = F_ACCUM | F_RELU;
            sgemm_kernel<<<dim3(HDIM / 128, gy, 1), 256>>>(tmp6, W2, b2, hnext,
                                                           NNODES, HDIM, HDIM, m);
        }
        // swap
        float* tswap = hcur; hcur = hnext; hnext = tswap;
    }

    // 3) output head on type 0 (hcur == hA after 2 swaps)
    {
        int blocks = (NNODES + 7) / 8;                // 8 warps per block
        head_kernel<<<blocks, 256>>>(hcur, Wout, bout, (float*)d_out);
    }
    (void)out_size; (void)n_in;
}

// round 5
// speedup vs baseline: 1.4250x; 1.4250x over previous
#include <cuda_runtime.h>
#include <cstdint>

// ---------------- problem constants ----------------
#define NNODES 20000
#define FIN    64
#define HDIM   512
#define NTYPES 5
#define TEDGE  6
#define NEDGE  160000
#define NH     (NNODES * HDIM)

// EDGE_TYPES = ((4,1),(1,0),(0,2),(2,3),(3,0),(1,4))
__constant__ int c_srcT[TEDGE] = {4, 1, 0, 2, 3, 1};

// ---------------- device scratch (no allocs allowed) ----------------
__device__ float g_hA[NTYPES * NH];
__device__ float g_hB[NTYPES * NH];
__device__ float g_agg6[TEDGE * NH];
__device__ float g_tmp6[TEDGE * NH];

#define F_RELU  1
#define F_ACCUM 2

struct GemmMap {
    long long aoff[TEDGE];
    long long boff[TEDGE];
    long long biasoff[TEDGE];
    long long coff[TEDGE];
    int       flags[TEDGE];
};

// ---------------- 3xTF32 tensor-core batched GEMM ----------------
// C[z](MxN) = op( A[z](MxK,row) @ B[z](KxN,row) + bias ), fp32-accurate via
// split tf32: A = Ah + Al, B = Bh + Bl; acc += Ah*Bh + Ah*Bl + Al*Bh.
// Block tile 128x128x32, 8 warps, warp tile 64x32, mma.m16n8k8.

#define ASTR 36   // A smem row stride (words): conflict-free fragment loads
#define BSTR 132  // B smem row stride (words): conflict-free fragment loads

#define SM_AH 0
#define SM_AL (128 * ASTR)
#define SM_BH (2 * 128 * ASTR)
#define SM_BL (2 * 128 * ASTR + 32 * BSTR)
#define SMEM_WORDS (2 * 128 * ASTR + 2 * 32 * BSTR)
#define SMEM_BYTES (SMEM_WORDS * 4)   // 70,656 bytes

__device__ __forceinline__ void split_tf32(float f, uint32_t& hi, uint32_t& lo) {
    asm("cvt.rna.tf32.f32 %0, %1;" : "=r"(hi) : "f"(f));
    float fl = f - __uint_as_float(hi);   // exact: tf32 value is fp32-representable
    asm("cvt.rna.tf32.f32 %0, %1;" : "=r"(lo) : "f"(fl));
}

__device__ __forceinline__ void mma_tf32(float* d, const uint32_t* a, const uint32_t* b) {
    asm volatile(
        "mma.sync.aligned.m16n8k8.row.col.f32.tf32.tf32.f32 "
        "{%0,%1,%2,%3}, {%4,%5,%6,%7}, {%8,%9}, {%0,%1,%2,%3};"
        : "+f"(d[0]), "+f"(d[1]), "+f"(d[2]), "+f"(d[3])
        : "r"(a[0]), "r"(a[1]), "r"(a[2]), "r"(a[3]), "r"(b[0]), "r"(b[1]));
}

__global__ __launch_bounds__(256, 1)
void tf32x3_gemm_kernel(const float* __restrict__ Ab, const float* __restrict__ Bb,
                        const float* __restrict__ biasb, float* __restrict__ Cb,
                        int M, int N, int K, GemmMap map)
{
    extern __shared__ uint32_t smem[];
    uint32_t* AsH = smem + SM_AH;
    uint32_t* AsL = smem + SM_AL;
    uint32_t* BsH = smem + SM_BH;
    uint32_t* BsL = smem + SM_BL;

    const int z = blockIdx.z;
    const float* __restrict__ A    = Ab    + map.aoff[z];
    const float* __restrict__ B    = Bb    + map.boff[z];
    const float* __restrict__ bias = biasb + map.biasoff[z];
    float* __restrict__       C    = Cb    + map.coff[z];
    const int flags = map.flags[z];

    const int tid  = threadIdx.x;
    const int warp = tid >> 5;
    const int lane = tid & 31;
    const int g = lane >> 2;            // group 0..7
    const int t = lane & 3;             // quad 0..3
    const int wm = (warp & 1) << 6;     // warp m offset: 0/64
    const int wn = (warp >> 1) << 5;    // warp n offset: 0/32/64/96
    const int bm = blockIdx.y << 7;
    const int bn = blockIdx.x << 7;

    float acc[4][4][4];
#pragma unroll
    for (int mi = 0; mi < 4; mi++)
#pragma unroll
        for (int ni = 0; ni < 4; ni++)
#pragma unroll
            for (int q = 0; q < 4; q++) acc[mi][ni][q] = 0.f;

    const int nk = K >> 5;              // 32-wide k tiles
    float4 aR[4], bR[4];

    // staging maps: A: id=tid+i*256 -> row=id>>3 (0..127), kq=id&7 ; B: row=id>>5, cq=id&31
    // ---- initial tile load ----
#pragma unroll
    for (int i = 0; i < 4; i++) {
        int id = tid + (i << 8);
        int ar = id >> 3, akq = id & 7;
        int gr = bm + ar;
        if (gr < M) aR[i] = *(const float4*)(A + (long long)gr * K + (akq << 2));
        else        aR[i] = make_float4(0.f, 0.f, 0.f, 0.f);
        int br = id >> 5, bcq = id & 31;
        bR[i] = *(const float4*)(B + (long long)br * N + bn + (bcq << 2));
    }
#pragma unroll
    for (int i = 0; i < 4; i++) {
        int id = tid + (i << 8);
        int ar = id >> 3, akq = id & 7;
        uint4 ah, al;
        split_tf32(aR[i].x, ah.x, al.x); split_tf32(aR[i].y, ah.y, al.y);
        split_tf32(aR[i].z, ah.z, al.z); split_tf32(aR[i].w, ah.w, al.w);
        *(uint4*)&AsH[ar * ASTR + (akq << 2)] = ah;
        *(uint4*)&AsL[ar * ASTR + (akq << 2)] = al;
        int br = id >> 5, bcq = id & 31;
        uint4 bh, bl;
        split_tf32(bR[i].x, bh.x, bl.x); split_tf32(bR[i].y, bh.y, bl.y);
        split_tf32(bR[i].z, bh.z, bl.z); split_tf32(bR[i].w, bh.w, bl.w);
        *(uint4*)&BsH[br * BSTR + (bcq << 2)] = bh;
        *(uint4*)&BsL[br * BSTR + (bcq << 2)] = bl;
    }
    __syncthreads();

    const int aBase = (wm + g) * ASTR + t;
    const int bBase = t * BSTR + wn + g;

    for (int kt = 0; kt < nk; kt++) {
        if (kt + 1 < nk) {
            const float* An = A + ((kt + 1) << 5);
            const float* Bn = B + (long long)((kt + 1) << 5) * N;
#pragma unroll
            for (int i = 0; i < 4; i++) {
                int id = tid + (i << 8);
                int ar = id >> 3, akq = id & 7;
                int gr = bm + ar;
                if (gr < M) aR[i] = *(const float4*)(An + (long long)gr * K + (akq << 2));
                else        aR[i] = make_float4(0.f, 0.f, 0.f, 0.f);
                int br = id >> 5, bcq = id & 31;
                bR[i] = *(const float4*)(Bn + (long long)br * N + bn + (bcq << 2));
            }
        }

#pragma unroll
        for (int ks = 0; ks < 4; ks++) {
            uint32_t afh[4][4], afl[4][4], bfh[4][2], bfl[4][2];
#pragma unroll
            for (int mi = 0; mi < 4; mi++) {
                int p = aBase + (mi << 4) * ASTR + (ks << 3);
                afh[mi][0] = AsH[p];               afl[mi][0] = AsL[p];
                afh[mi][1] = AsH[p + 8 * ASTR];    afl[mi][1] = AsL[p + 8 * ASTR];
                afh[mi][2] = AsH[p + 4];           afl[mi][2] = AsL[p + 4];
                afh[mi][3] = AsH[p + 8 * ASTR + 4]; afl[mi][3] = AsL[p + 8 * ASTR + 4];
            }
#pragma unroll
            for (int ni = 0; ni < 4; ni++) {
                int p = bBase + (ks << 3) * BSTR + (ni << 3);
                bfh[ni][0] = BsH[p];               bfl[ni][0] = BsL[p];
                bfh[ni][1] = BsH[p + 4 * BSTR];    bfl[ni][1] = BsL[p + 4 * BSTR];
            }
#pragma unroll
            for (int mi = 0; mi < 4; mi++)
#pragma unroll
                for (int ni = 0; ni < 4; ni++) {
                    mma_tf32(acc[mi][ni], afh[mi], bfh[ni]);   // hi*hi
                    mma_tf32(acc[mi][ni], afh[mi], bfl[ni]);   // hi*lo
                    mma_tf32(acc[mi][ni], afl[mi], bfh[ni]);   // lo*hi
                }
        }
        __syncthreads();

        if (kt + 1 < nk) {
#pragma unroll
            for (int i = 0; i < 4; i++) {
                int id = tid + (i << 8);
                int ar = id >> 3, akq = id & 7;
                uint4 ah, al;
                split_tf32(aR[i].x, ah.x, al.x); split_tf32(aR[i].y, ah.y, al.y);
                split_tf32(aR[i].z, ah.z, al.z); split_tf32(aR[i].w, ah.w, al.w);
                *(uint4*)&AsH[ar * ASTR + (akq << 2)] = ah;
                *(uint4*)&AsL[ar * ASTR + (akq << 2)] = al;
                int br = id >> 5, bcq = id & 31;
                uint4 bh, bl;
                split_tf32(bR[i].x, bh.x, bl.x); split_tf32(bR[i].y, bh.y, bl.y);
                split_tf32(bR[i].z, bh.z, bl.z); split_tf32(bR[i].w, bh.w, bl.w);
                *(uint4*)&BsH[br * BSTR + (bcq << 2)] = bh;
                *(uint4*)&BsL[br * BSTR + (bcq << 2)] = bl;
            }
            __syncthreads();
        }
    }

    // ---- epilogue: bias + (accum) + (relu) ----
    float2 bia[4];
#pragma unroll
    for (int ni = 0; ni < 4; ni++)
        bia[ni] = *(const float2*)(bias + bn + wn + (ni << 3) + (t << 1));

#pragma unroll
    for (int mi = 0; mi < 4; mi++) {
        int r0 = bm + wm + (mi << 4) + g;
        int r1 = r0 + 8;
#pragma unroll
        for (int ni = 0; ni < 4; ni++) {
            int col = bn + wn + (ni << 3) + (t << 1);
#pragma unroll
            for (int h = 0; h < 2; h++) {
                int r = h ? r1 : r0;
                if (r >= M) continue;
                float2 v;
                v.x = acc[mi][ni][h ? 2 : 0] + bia[ni].x;
                v.y = acc[mi][ni][h ? 3 : 1] + bia[ni].y;
                float* cp = C + (long long)r * N + col;
                if (flags & F_ACCUM) {
                    float2 o = *(const float2*)cp;
                    v.x += o.x; v.y += o.y;
                }
                if (flags & F_RELU) {
                    v.x = fmaxf(v.x, 0.f);
                    v.y = fmaxf(v.y, 0.f);
                }
                *(float2*)cp = v;
            }
        }
    }
}

// ---------------- scatter: agg6[t][dst] += h[srcT[t]][src], one warp per edge ----------------
__global__ void scatter_kernel(const float* __restrict__ h, float* __restrict__ agg6,
                               const int* __restrict__ edges /* [6][2][NEDGE] */)
{
    int gw   = (blockIdx.x * blockDim.x + threadIdx.x) >> 5;
    int lane = threadIdx.x & 31;
    if (gw >= TEDGE * NEDGE) return;
    int t = gw / NEDGE;
    int e = gw - t * NEDGE;
    const int* src = edges + (long long)t * 2 * NEDGE;
    const int* dst = src + NEDGE;
    int sn = __ldg(src + e);
    int dn = __ldg(dst + e);
    int st = c_srcT[t];

    const float4* srow = (const float4*)(h + ((long long)st * NNODES + sn) * HDIM);
    float* arow = agg6 + ((long long)t * NNODES + dn) * HDIM;
#pragma unroll
    for (int k = 0; k < 4; k++) {
        float4 v = __ldg(srow + lane + (k << 5));
        float* p = arow + ((lane + (k << 5)) << 2);
        asm volatile("red.global.add.v4.f32 [%0], {%1,%2,%3,%4};"
                     :: "l"(p), "f"(v.x), "f"(v.y), "f"(v.z), "f"(v.w)
                     : "memory");
    }
}

// ---------------- output head ----------------
__global__ void head_kernel(const float* __restrict__ h0, const float* __restrict__ Wout,
                            const float* __restrict__ bout, float* __restrict__ out)
{
    int node = (blockIdx.x * blockDim.x + threadIdx.x) >> 5;
    int lane = threadIdx.x & 31;
    if (node >= NNODES) return;
    const float4* row = (const float4*)(h0 + (long long)node * HDIM);
    const float4* w4  = (const float4*)Wout;
    float s = 0.f;
#pragma unroll
    for (int k = 0; k < 4; k++) {
        float4 a = row[lane + (k << 5)];
        float4 w = __ldg(w4 + lane + (k << 5));
        s += a.x * w.x + a.y * w.y + a.z * w.z + a.w * w.w;
    }
#pragma unroll
    for (int off = 16; off; off >>= 1) s += __shfl_down_sync(0xffffffffu, s, off);
    if (lane == 0) out[node] = s + bout[0];
}

// ---------------- host launch ----------------
extern "C" void kernel_launch(void* const* d_in, const int* in_sizes, int n_in,
                              void* d_out, int out_size)
{
    const float *x = nullptr, *Win = nullptr, *bin = nullptr;
    const float *W1 = nullptr, *b1 = nullptr, *W2 = nullptr, *b2 = nullptr;
    const float *Wout = nullptr, *bout = nullptr;
    const int* edges = nullptr;

    for (int i = 0; i < n_in; i++) {
        int s = in_sizes[i];
        const void* p = d_in[i];
        switch (s) {
            case 6400000: x    = (const float*)p; break;
            case 163840:  Win  = (const float*)p; break;
            case 2560:    bin  = (const float*)p; break;
            case 3145728: if (!W1) W1 = (const float*)p; else W2 = (const float*)p; break;
            case 6144:    if (!b1) b1 = (const float*)p; else b2 = (const float*)p; break;
            case 512:     Wout = (const float*)p; break;
            case 1:       bout = (const float*)p; break;
            case 1920000: edges = (const int*)p; break;
        }
    }

    static bool attr_done = false;
    if (!attr_done) {
        cudaFuncSetAttribute(tf32x3_gemm_kernel,
                             cudaFuncAttributeMaxDynamicSharedMemorySize, SMEM_BYTES);
        attr_done = true;
    }

    float *hA, *hB, *agg6, *tmp6;
    cudaGetSymbolAddress((void**)&hA,   g_hA);
    cudaGetSymbolAddress((void**)&hB,   g_hB);
    cudaGetSymbolAddress((void**)&agg6, g_agg6);
    cudaGetSymbolAddress((void**)&tmp6, g_tmp6);

    const int gy = (NNODES + 127) / 128;   // 157
    const int dstT[TEDGE] = {1, 0, 2, 3, 0, 4};

    // 1) input projection: h = relu(x @ W_in + b_in), batched over 5 types (K=64)
    {
        GemmMap m = {};
        for (int t = 0; t < NTYPES; t++) {
            m.aoff[t]    = (long long)t * NNODES * FIN;
            m.boff[t]    = (long long)t * FIN * HDIM;
            m.biasoff[t] = (long long)t * HDIM;
            m.coff[t]    = (long long)t * NH;
            m.flags[t]   = F_RELU;
        }
        tf32x3_gemm_kernel<<<dim3(HDIM / 128, gy, NTYPES), 256, SMEM_BYTES>>>(
            x, Win, bin, hA, NNODES, HDIM, FIN, m);
    }

    float* hcur = hA;
    float* hnext = hB;

    for (int l = 0; l < 2; l++) {
        // 2a) agg init: agg6[t] = h[dstT[t]]
        for (int t = 0; t < TEDGE; t++) {
            cudaMemcpyAsync(agg6 + (long long)t * NH, hcur + (long long)dstT[t] * NH,
                            (size_t)NH * sizeof(float), cudaMemcpyDeviceToDevice);
        }
        // 2b) scatter-add over all 6 edge types
        {
            int warps = TEDGE * NEDGE;
            int blocks = (warps + 7) / 8;
            scatter_kernel<<<blocks, 256>>>(hcur, agg6, edges);
        }
        // 2c) GEMM1: tmp6[t] = relu(agg6[t] @ W1[l,t] + b1[l,t])
        {
            GemmMap m = {};
            for (int t = 0; t < TEDGE; t++) {
                m.aoff[t]    = (long long)t * NH;
                m.boff[t]    = ((long long)l * TEDGE + t) * HDIM * HDIM;
                m.biasoff[t] = ((long long)l * TEDGE + t) * HDIM;
                m.coff[t]    = (long long)t * NH;
                m.flags[t]   = F_RELU;
            }
            tf32x3_gemm_kernel<<<dim3(HDIM / 128, gy, TEDGE), 256, SMEM_BYTES>>>(
                agg6, W1, b1, tmp6, NNODES, HDIM, HDIM, m);
        }
        // 2d) GEMM2 group 1: t in {0,1,2,3,5}; t=1 (dst 0) stays raw for t=4 accum
        {
            GemmMap m = {};
            const int zs[5] = {0, 1, 2, 3, 5};
            for (int zi = 0; zi < 5; zi++) {
                int t = zs[zi];
                m.aoff[zi]    = (long long)t * NH;
                m.boff[zi]    = ((long long)l * TEDGE + t) * HDIM * HDIM;
                m.biasoff[zi] = ((long long)l * TEDGE + t) * HDIM;
                m.coff[zi]    = (long long)dstT[t] * NH;
                m.flags[zi]   = (t == 1) ? 0 : F_RELU;
            }
            tf32x3_gemm_kernel<<<dim3(HDIM / 128, gy, 5), 256, SMEM_BYTES>>>(
                tmp6, W2, b2, hnext, NNODES, HDIM, HDIM, m);
        }
        // 2e) GEMM2 group 2: t=4 accumulates into dst 0, then relu
        {
            GemmMap m = {};
            m.aoff[0]    = (long long)4 * NH;
            m.boff[0]    = ((long long)l * TEDGE + 4) * HDIM * HDIM;
            m.biasoff[0] = ((long long)l * TEDGE + 4) * HDIM;
            m.coff[0]    = 0;
            m.flags[0]   = F_ACCUM | F_RELU;
            tf32x3_gemm_kernel<<<dim3(HDIM / 128, gy, 1), 256, SMEM_BYTES>>>(
                tmp6, W2, b2, hnext, NNODES, HDIM, HDIM, m);
        }
        float* tswap = hcur; hcur = hnext; hnext = tswap;
    }

    // 3) output head on type 0
    {
        int blocks = (NNODES + 7) / 8;
        head_kernel<<<blocks, 256>>>(hcur, Wout, bout, (float*)d_out);
    }
    (void)out_size; (void)n_in;
}

// round 7
// speedup vs baseline: 1.6756x; 1.1758x over previous
#include <cuda_runtime.h>
#include <cstdint>

// ---------------- problem constants ----------------
#define NNODES 20000
#define FIN    64
#define HDIM   512
#define NTYPES 5
#define TEDGE  6
#define NEDGE  160000
#define NH     (NNODES * HDIM)

// EDGE_TYPES = ((4,1),(1,0),(0,2),(2,3),(3,0),(1,4))
__constant__ int c_srcT[TEDGE] = {4, 1, 0, 2, 3, 1};
__constant__ int c_dstT[TEDGE] = {1, 0, 2, 3, 0, 4};

// ---------------- device scratch (no allocs allowed) ----------------
__device__ float g_hA[NTYPES * NH];
__device__ float g_hB[NTYPES * NH];
__device__ float g_agg6[TEDGE * NH];
__device__ float g_tmp6[TEDGE * NH];
__device__ int   g_cnt[TEDGE * NNODES];
__device__ int   g_fill[TEDGE * NNODES];
__device__ int   g_indptr[TEDGE * (NNODES + 1)];
__device__ int   g_esrc[TEDGE * NEDGE];

#define F_RELU  1
#define F_ACCUM 2

struct GemmMap {
    long long aoff[TEDGE];
    long long boff[TEDGE];
    long long biasoff[TEDGE];
    long long coff[TEDGE];
    int       flags[TEDGE];
};

// ---------------- 3xTF32 tensor-core batched GEMM (double-buffered) ----------------
// C[z](MxN) = op( A[z](MxK,row) @ B[z](KxN,row) + bias ), fp32-accurate via
// split tf32: A = Ah + Al, B = Bh + Bl; acc += Ah*Bh + Ah*Bl + Al*Bh.
// Block tile 128x128x32, 8 warps, warp tile 64x32, mma.m16n8k8.

#define ASTR 36   // A smem row stride (words): conflict-free fragment loads
#define BSTR 132  // B smem row stride (words): conflict-free fragment loads

#define SM_AH 0
#define SM_AL (128 * ASTR)
#define SM_BH (2 * 128 * ASTR)
#define SM_BL (2 * 128 * ASTR + 32 * BSTR)
#define SMEM_WORDS (2 * 128 * ASTR + 2 * 32 * BSTR)   // one buffer: 17,664 words
#define SMEM_BYTES (2 * SMEM_WORDS * 4)               // double buffered: 141,312 B

__device__ __forceinline__ void split_tf32(float f, uint32_t& hi, uint32_t& lo) {
    asm("cvt.rna.tf32.f32 %0, %1;" : "=r"(hi) : "f"(f));
    float fl = f - __uint_as_float(hi);   // exact: tf32 value is fp32-representable
    asm("cvt.rna.tf32.f32 %0, %1;" : "=r"(lo) : "f"(fl));
}

__device__ __forceinline__ void mma_tf32(float* d, const uint32_t* a, const uint32_t* b) {
    asm volatile(
        "mma.sync.aligned.m16n8k8.row.col.f32.tf32.tf32.f32 "
        "{%0,%1,%2,%3}, {%4,%5,%6,%7}, {%8,%9}, {%0,%1,%2,%3};"
        : "+f"(d[0]), "+f"(d[1]), "+f"(d[2]), "+f"(d[3])
        : "r"(a[0]), "r"(a[1]), "r"(a[2]), "r"(a[3]), "r"(b[0]), "r"(b[1]));
}

__global__ __launch_bounds__(256, 1)
void tf32x3_gemm_kernel(const float* __restrict__ Ab, const float* __restrict__ Bb,
                        const float* __restrict__ biasb, float* __restrict__ Cb,
                        int M, int N, int K, GemmMap map)
{
    extern __shared__ uint32_t smem[];

    const int z = blockIdx.z;
    const float* __restrict__ A    = Ab    + map.aoff[z];
    const float* __restrict__ B    = Bb    + map.boff[z];
    const float* __restrict__ bias = biasb + map.biasoff[z];
    float* __restrict__       C    = Cb    + map.coff[z];
    const int flags = map.flags[z];

    const int tid  = threadIdx.x;
    const int warp = tid >> 5;
    const int lane = tid & 31;
    const int g = lane >> 2;            // group 0..7
    const int t = lane & 3;             // quad 0..3
    const int wm = (warp & 1) << 6;     // warp m offset: 0/64
    const int wn = (warp >> 1) << 5;    // warp n offset: 0/32/64/96
    const int bm = blockIdx.y << 7;
    const int bn = blockIdx.x << 7;

    float acc[4][4][4];
#pragma unroll
    for (int mi = 0; mi < 4; mi++)
#pragma unroll
        for (int ni = 0; ni < 4; ni++)
#pragma unroll
            for (int q = 0; q < 4; q++) acc[mi][ni][q] = 0.f;

    const int nk = K >> 5;              // 32-wide k tiles
    float4 aR[4], bR[4];

    // staging maps: A: id=tid+i*256 -> row=id>>3 (0..127), kq=id&7 ; B: row=id>>5, cq=id&31
    // ---- prologue: tile 0 -> buffer 0 ----
#pragma unroll
    for (int i = 0; i < 4; i++) {
        int id = tid + (i << 8);
        int ar = id >> 3, akq = id & 7;
        int gr = bm + ar;
        if (gr < M) aR[i] = *(const float4*)(A + (long long)gr * K + (akq << 2));
        else        aR[i] = make_float4(0.f, 0.f, 0.f, 0.f);
        int br = id >> 5, bcq = id & 31;
        bR[i] = *(const float4*)(B + (long long)br * N + bn + (bcq << 2));
    }
#pragma unroll
    for (int i = 0; i < 4; i++) {
        int id = tid + (i << 8);
        int ar = id >> 3, akq = id & 7;
        uint4 ah, al;
        split_tf32(aR[i].x, ah.x, al.x); split_tf32(aR[i].y, ah.y, al.y);
        split_tf32(aR[i].z, ah.z, al.z); split_tf32(aR[i].w, ah.w, al.w);
        *(uint4*)&smem[SM_AH + ar * ASTR + (akq << 2)] = ah;
        *(uint4*)&smem[SM_AL + ar * ASTR + (akq << 2)] = al;
        int br = id >> 5, bcq = id & 31;
        uint4 bh, bl;
        split_tf32(bR[i].x, bh.x, bl.x); split_tf32(bR[i].y, bh.y, bl.y);
        split_tf32(bR[i].z, bh.z, bl.z); split_tf32(bR[i].w, bh.w, bl.w);
        *(uint4*)&smem[SM_BH + br * BSTR + (bcq << 2)] = bh;
        *(uint4*)&smem[SM_BL + br * BSTR + (bcq << 2)] = bl;
    }
    __syncthreads();

    const int aBase = (wm + g) * ASTR + t;
    const int bBase = t * BSTR + wn + g;
    int bufOff = 0;

    for (int kt = 0; kt < nk; kt++) {
        // issue next-tile global loads first (latency overlapped by MMA below)
        if (kt + 1 < nk) {
            const float* An = A + ((kt + 1) << 5);
            const float* Bn = B + (long long)((kt + 1) << 5) * N;
#pragma unroll
            for (int i = 0; i < 4; i++) {
                int id = tid + (i << 8);
                int ar = id >> 3, akq = id & 7;
                int gr = bm + ar;
                if (gr < M) aR[i] = *(const float4*)(An + (long long)gr * K + (akq << 2));
                else        aR[i] = make_float4(0.f, 0.f, 0.f, 0.f);
                int br = id >> 5, bcq = id & 31;
                bR[i] = *(const float4*)(Bn + (long long)br * N + bn + (bcq << 2));
            }
        }

        // ---- MMA on current buffer ----
        const uint32_t* AsH = smem + bufOff + SM_AH;
        const uint32_t* AsL = smem + bufOff + SM_AL;
        const uint32_t* BsH = smem + bufOff + SM_BH;
        const uint32_t* BsL = smem + bufOff + SM_BL;
#pragma unroll
        for (int ks = 0; ks < 4; ks++) {
            uint32_t afh[4][4], afl[4][4], bfh[4][2], bfl[4][2];
#pragma unroll
            for (int mi = 0; mi < 4; mi++) {
                int p = aBase + (mi << 4) * ASTR + (ks << 3);
                afh[mi][0] = AsH[p];                afl[mi][0] = AsL[p];
                afh[mi][1] = AsH[p + 8 * ASTR];     afl[mi][1] = AsL[p + 8 * ASTR];
                afh[mi][2] = AsH[p + 4];            afl[mi][2] = AsL[p + 4];
                afh[mi][3] = AsH[p + 8 * ASTR + 4]; afl[mi][3] = AsL[p + 8 * ASTR + 4];
            }
#pragma unroll
            for (int ni = 0; ni < 4; ni++) {
                int p = bBase + (ks << 3) * BSTR + (ni << 3);
                bfh[ni][0] = BsH[p];                bfl[ni][0] = BsL[p];
                bfh[ni][1] = BsH[p + 4 * BSTR];     bfl[ni][1] = BsL[p + 4 * BSTR];
            }
#pragma unroll
            for (int mi = 0; mi < 4; mi++)
#pragma unroll
                for (int ni = 0; ni < 4; ni++) {
                    mma_tf32(acc[mi][ni], afh[mi], bfh[ni]);   // hi*hi
                    mma_tf32(acc[mi][ni], afh[mi], bfl[ni]);   // hi*lo
                    mma_tf32(acc[mi][ni], afl[mi], bfh[ni]);   // lo*hi
                }
        }

        // ---- split/store next tile into the other buffer ----
        if (kt + 1 < nk) {
            int nOff = bufOff ^ SMEM_WORDS;
#pragma unroll
            for (int i = 0; i < 4; i++) {
                int id = tid + (i << 8);
                int ar = id >> 3, akq = id & 7;
                uint4 ah, al;
                split_tf32(aR[i].x, ah.x, al.x); split_tf32(aR[i].y, ah.y, al.y);
                split_tf32(aR[i].z, ah.z, al.z); split_tf32(aR[i].w, ah.w, al.w);
                *(uint4*)&smem[nOff + SM_AH + ar * ASTR + (akq << 2)] = ah;
                *(uint4*)&smem[nOff + SM_AL + ar * ASTR + (akq << 2)] = al;
                int br = id >> 5, bcq = id & 31;
                uint4 bh, bl;
                split_tf32(bR[i].x, bh.x, bl.x); split_tf32(bR[i].y, bh.y, bl.y);
                split_tf32(bR[i].z, bh.z, bl.z); split_tf32(bR[i].w, bh.w, bl.w);
                *(uint4*)&smem[nOff + SM_BH + br * BSTR + (bcq << 2)] = bh;
                *(uint4*)&smem[nOff + SM_BL + br * BSTR + (bcq << 2)] = bl;
            }
        }
        __syncthreads();
        bufOff ^= SMEM_WORDS;
    }

    // ---- epilogue: bias + (accum) + (relu) ----
    float2 bia[4];
#pragma unroll
    for (int ni = 0; ni < 4; ni++)
        bia[ni] = *(const float2*)(bias + bn + wn + (ni << 3) + (t << 1));

#pragma unroll
    for (int mi = 0; mi < 4; mi++) {
        int r0 = bm + wm + (mi << 4) + g;
        int r1 = r0 + 8;
#pragma unroll
        for (int ni = 0; ni < 4; ni++) {
            int col = bn + wn + (ni << 3) + (t << 1);
#pragma unroll
            for (int h = 0; h < 2; h++) {
                int r = h ? r1 : r0;
                if (r >= M) continue;
                float2 v;
                v.x = acc[mi][ni][h ? 2 : 0] + bia[ni].x;
                v.y = acc[mi][ni][h ? 3 : 1] + bia[ni].y;
                float* cp = C + (long long)r * N + col;
                if (flags & F_ACCUM) {
                    float2 o = *(const float2*)cp;
                    v.x += o.x; v.y += o.y;
                }
                if (flags & F_RELU) {
                    v.x = fmaxf(v.x, 0.f);
                    v.y = fmaxf(v.y, 0.f);
                }
                *(float2*)cp = v;
            }
        }
    }
}

// ---------------- CSR build: count -> scan -> fill ----------------
__global__ void count_kernel(const int* __restrict__ edges, int* __restrict__ cnt)
{
    int idx = blockIdx.x * blockDim.x + threadIdx.x;
    if (idx >= TEDGE * NEDGE) return;
    int t = idx / NEDGE;
    int e = idx - t * NEDGE;
    int dn = __ldg(edges + (long long)t * 2 * NEDGE + NEDGE + e);
    atomicAdd(&cnt[t * NNODES + dn], 1);
}

__global__ void scan_kernel(const int* __restrict__ cnt, int* __restrict__ indptr,
                            int* __restrict__ fill)
{
    __shared__ int sh[1024];
    __shared__ int run;
    int t = blockIdx.x;
    if (threadIdx.x == 0) { run = 0; indptr[t * (NNODES + 1)] = 0; }
    __syncthreads();
    const int* c = cnt + t * NNODES;
    int* ip = indptr + t * (NNODES + 1);
    for (int base = 0; base < NNODES; base += 1024) {
        int i = base + threadIdx.x;
        int v = (i < NNODES) ? c[i] : 0;
        sh[threadIdx.x] = v;
        __syncthreads();
        for (int off = 1; off < 1024; off <<= 1) {
            int x = (threadIdx.x >= off) ? sh[threadIdx.x - off] : 0;
            __syncthreads();
            sh[threadIdx.x] += x;
            __syncthreads();
        }
        if (i < NNODES) ip[i + 1] = run + sh[threadIdx.x];
        __syncthreads();
        if (threadIdx.x == 0) run += sh[1023];
        __syncthreads();
    }
    for (int i = threadIdx.x; i < NNODES; i += 1024)
        fill[t * NNODES + i] = ip[i];
}

__global__ void fill_kernel(const int* __restrict__ edges, int* __restrict__ fill,
                            int* __restrict__ esrc)
{
    int idx = blockIdx.x * blockDim.x + threadIdx.x;
    if (idx >= TEDGE * NEDGE) return;
    int t = idx / NEDGE;
    int e = idx - t * NEDGE;
    const int* base = edges + (long long)t * 2 * NEDGE;
    int sn = __ldg(base + e);
    int dn = __ldg(base + NEDGE + e);
    int pos = atomicAdd(&fill[t * NNODES + dn], 1);
    esrc[t * NEDGE + pos] = sn;
}

// ---------------- gather: agg6[t][n] = h[dstT[t]][n] + sum_{s in adj} h[srcT[t]][s] ----
__global__ void gather_kernel(const float* __restrict__ h, float* __restrict__ agg6,
                              const int* __restrict__ indptr, const int* __restrict__ esrc)
{
    int gw   = (blockIdx.x * blockDim.x + threadIdx.x) >> 5;
    int lane = threadIdx.x & 31;
    if (gw >= TEDGE * NNODES) return;
    int t = gw / NNODES;
    int node = gw - t * NNODES;
    int beg = __ldg(indptr + t * (NNODES + 1) + node);
    int end = __ldg(indptr + t * (NNODES + 1) + node + 1);

    // seed with h[dstT[t]][node] (fused copy)
    const float4* drow = (const float4*)(h + ((long long)c_dstT[t] * NNODES + node) * HDIM);
    float4 a0 = __ldg(drow + lane);
    float4 a1 = __ldg(drow + lane + 32);
    float4 a2 = __ldg(drow + lane + 64);
    float4 a3 = __ldg(drow + lane + 96);

    const float* hsrc = h + (long long)c_srcT[t] * NNODES * HDIM;
    const int* el = esrc + (long long)t * NEDGE;

    int j = beg;
    for (; j + 1 < end; j += 2) {
        int s0 = __ldg(el + j);
        int s1 = __ldg(el + j + 1);
        const float4* r0 = (const float4*)(hsrc + (long long)s0 * HDIM);
        const float4* r1 = (const float4*)(hsrc + (long long)s1 * HDIM);
        float4 p0 = __ldg(r0 + lane),      q0 = __ldg(r1 + lane);
        float4 p1 = __ldg(r0 + lane + 32), q1 = __ldg(r1 + lane + 32);
        float4 p2 = __ldg(r0 + lane + 64), q2 = __ldg(r1 + lane + 64);
        float4 p3 = __ldg(r0 + lane + 96), q3 = __ldg(r1 + lane + 96);
        a0.x += p0.x + q0.x; a0.y += p0.y + q0.y; a0.z += p0.z + q0.z; a0.w += p0.w + q0.w;
        a1.x += p1.x + q1.x; a1.y += p1.y + q1.y; a1.z += p1.z + q1.z; a1.w += p1.w + q1.w;
        a2.x += p2.x + q2.x; a2.y += p2.y + q2.y; a2.z += p2.z + q2.z; a2.w += p2.w + q2.w;
        a3.x += p3.x + q3.x; a3.y += p3.y + q3.y; a3.z += p3.z + q3.z; a3.w += p3.w + q3.w;
    }
    if (j < end) {
        int s0 = __ldg(el + j);
        const float4* r0 = (const float4*)(hsrc + (long long)s0 * HDIM);
        float4 p0 = __ldg(r0 + lane);
        float4 p1 = __ldg(r0 + lane + 32);
        float4 p2 = __ldg(r0 + lane + 64);
        float4 p3 = __ldg(r0 + lane + 96);
        a0.x += p0.x; a0.y += p0.y; a0.z += p0.z; a0.w += p0.w;
        a1.x += p1.x; a1.y += p1.y; a1.z += p1.z; a1.w += p1.w;
        a2.x += p2.x; a2.y += p2.y; a2.z += p2.z; a2.w += p2.w;
        a3.x += p3.x; a3.y += p3.y; a3.z += p3.z; a3.w += p3.w;
    }

    float4* arow = (float4*)(agg6 + ((long long)t * NNODES + node) * HDIM);
    arow[lane]      = a0;
    arow[lane + 32] = a1;
    arow[lane + 64] = a2;
    arow[lane + 96] = a3;
}

// ---------------- output head ----------------
__global__ void head_kernel(const float* __restrict__ h0, const float* __restrict__ Wout,
                            const float* __restrict__ bout, float* __restrict__ out)
{
    int node = (blockIdx.x * blockDim.x + threadIdx.x) >> 5;
    int lane = threadIdx.x & 31;
    if (node >= NNODES) return;
    const float4* row = (const float4*)(h0 + (long long)node * HDIM);
    const float4* w4  = (const float4*)Wout;
    float s = 0.f;
#pragma unroll
    for (int k = 0; k < 4; k++) {
        float4 a = row[lane + (k << 5)];
        float4 w = __ldg(w4 + lane + (k << 5));
        s += a.x * w.x + a.y * w.y + a.z * w.z + a.w * w.w;
    }
#pragma unroll
    for (int off = 16; off; off >>= 1) s += __shfl_down_sync(0xffffffffu, s, off);
    if (lane == 0) out[node] = s + bout[0];
}

// ---------------- host launch ----------------
extern "C" void kernel_launch(void* const* d_in, const int* in_sizes, int n_in,
                              void* d_out, int out_size)
{
    const float *x = nullptr, *Win = nullptr, *bin = nullptr;
    const float *W1 = nullptr, *b1 = nullptr, *W2 = nullptr, *b2 = nullptr;
    const float *Wout = nullptr, *bout = nullptr;
    const int* edges = nullptr;

    for (int i = 0; i < n_in; i++) {
        int s = in_sizes[i];
        const void* p = d_in[i];
        switch (s) {
            case 6400000: x    = (const float*)p; break;
            case 163840:  Win  = (const float*)p; break;
            case 2560:    bin  = (const float*)p; break;
            case 3145728: if (!W1) W1 = (const float*)p; else W2 = (const float*)p; break;
            case 6144:    if (!b1) b1 = (const float*)p; else b2 = (const float*)p; break;
            case 512:     Wout = (const float*)p; break;
            case 1:       bout = (const float*)p; break;
            case 1920000: edges = (const int*)p; break;
        }
    }

    static bool attr_done = false;
    if (!attr_done) {
        cudaFuncSetAttribute(tf32x3_gemm_kernel,
                             cudaFuncAttributeMaxDynamicSharedMemorySize, SMEM_BYTES);
        attr_done = true;
    }

    float *hA, *hB, *agg6, *tmp6;
    int *cnt, *fillp, *indptr, *esrc;
    cudaGetSymbolAddress((void**)&hA,     g_hA);
    cudaGetSymbolAddress((void**)&hB,     g_hB);
    cudaGetSymbolAddress((void**)&agg6,   g_agg6);
    cudaGetSymbolAddress((void**)&tmp6,   g_tmp6);
    cudaGetSymbolAddress((void**)&cnt,    g_cnt);
    cudaGetSymbolAddress((void**)&fillp,  g_fill);
    cudaGetSymbolAddress((void**)&indptr, g_indptr);
    cudaGetSymbolAddress((void**)&esrc,   g_esrc);

    const int gy = (NNODES + 127) / 128;   // 157
    const int dstT[TEDGE] = {1, 0, 2, 3, 0, 4};

    // 0) CSR build (edge structure is layer-independent; build once per launch)
    cudaMemsetAsync(cnt, 0, (size_t)TEDGE * NNODES * sizeof(int));
    count_kernel<<<(TEDGE * NEDGE + 255) / 256, 256>>>(edges, cnt);
    scan_kernel<<<TEDGE, 1024>>>(cnt, indptr, fillp);
    fill_kernel<<<(TEDGE * NEDGE + 255) / 256, 256>>>(edges, fillp, esrc);

    // 1) input projection: h = relu(x @ W_in + b_in), batched over 5 types (K=64)
    {
        GemmMap m = {};
        for (int t = 0; t < NTYPES; t++) {
            m.aoff[t]    = (long long)t * NNODES * FIN;
            m.boff[t]    = (long long)t * FIN * HDIM;
            m.biasoff[t] = (long long)t * HDIM;
            m.coff[t]    = (long long)t * NH;
            m.flags[t]   = F_RELU;
        }
        tf32x3_gemm_kernel<<<dim3(HDIM / 128, gy, NTYPES), 256, SMEM_BYTES>>>(
            x, Win, bin, hA, NNODES, HDIM, FIN, m);
    }

    float* hcur = hA;
    float* hnext = hB;

    for (int l = 0; l < 2; l++) {
        // 2a+2b) fused gather: agg6[t] = h[dstT[t]] + segment_sum(h[srcT[t]])
        {
            int warps = TEDGE * NNODES;               // 120000
            int blocks = (warps + 7) / 8;
            gather_kernel<<<blocks, 256>>>(hcur, agg6, indptr, esrc);
        }
        // 2c) GEMM1: tmp6[t] = relu(agg6[t] @ W1[l,t] + b1[l,t])
        {
            GemmMap m = {};
            for (int t = 0; t < TEDGE; t++) {
                m.aoff[t]    = (long long)t * NH;
                m.boff[t]    = ((long long)l * TEDGE + t) * HDIM * HDIM;
                m.biasoff[t] = ((long long)l * TEDGE + t) * HDIM;
                m.coff[t]    = (long long)t * NH;
                m.flags[t]   = F_RELU;
            }
            tf32x3_gemm_kernel<<<dim3(HDIM / 128, gy, TEDGE), 256, SMEM_BYTES>>>(
                agg6, W1, b1, tmp6, NNODES, HDIM, HDIM, m);
        }
        // 2d) GEMM2 group 1: t in {0,1,2,3,5}; t=1 (dst 0) stays raw for t=4 accum
        {
            GemmMap m = {};
            const int zs[5] = {0, 1, 2, 3, 5};
            for (int zi = 0; zi < 5; zi++) {
                int t = zs[zi];
                m.aoff[zi]    = (long long)t * NH;
                m.boff[zi]    = ((long long)l * TEDGE + t) * HDIM * HDIM;
                m.biasoff[zi] = ((long long)l * TEDGE + t) * HDIM;
                m.coff[zi]    = (long long)dstT[t] * NH;
                m.flags[zi]   = (t == 1) ? 0 : F_RELU;
            }
            tf32x3_gemm_kernel<<<dim3(HDIM / 128, gy, 5), 256, SMEM_BYTES>>>(
                tmp6, W2, b2, hnext, NNODES, HDIM, HDIM, m);
        }
        // 2e) GEMM2 group 2: t=4 accumulates into dst 0, then relu
        {
            GemmMap m = {};
            m.aoff[0]    = (long long)4 * NH;
            m.boff[0]    = ((long long)l * TEDGE + 4) * HDIM * HDIM;
            m.biasoff[0] = ((long long)l * TEDGE + 4) * HDIM;
            m.coff[0]    = 0;
            m.flags[0]   = F_ACCUM | F_RELU;
            tf32x3_gemm_kernel<<<dim3(HDIM / 128, gy, 1), 256, SMEM_BYTES>>>(
                tmp6, W2, b2, hnext, NNODES, HDIM, HDIM, m);
        }
        float* tswap = hcur; hcur = hnext; hnext = tswap;
    }

    // 3) output head on type 0
    {
        int blocks = (NNODES + 7) / 8;
        head_kernel<<<blocks, 256>>>(hcur, Wout, bout, (float*)d_out);
    }
    (void)out_size; (void)n_in;
}

// round 9
// speedup vs baseline: 2.6192x; 1.5632x over previous
#include <cuda_runtime.h>
#include <cstdint>

// ---------------- problem constants ----------------
#define NNODES 20000
#define FIN    64
#define HDIM   512
#define NTYPES 5
#define TEDGE  6
#define NEDGE  160000
#define NH     (NNODES * HDIM)

// EDGE_TYPES = ((4,1),(1,0),(0,2),(2,3),(3,0),(1,4))
__constant__ int c_srcT[TEDGE] = {4, 1, 0, 2, 3, 1};
__constant__ int c_dstT[TEDGE] = {1, 0, 2, 3, 0, 4};

// ---------------- device scratch (no allocs allowed) ----------------
__device__ float g_hA[NTYPES * NH];
__device__ float g_hB[NTYPES * NH];
__device__ float g_agg6[TEDGE * NH];
__device__ float g_tmp6[TEDGE * NH];
__device__ int   g_cnt[TEDGE * NNODES];
__device__ int   g_fill[TEDGE * NNODES];
__device__ int   g_indptr[TEDGE * (NNODES + 1)];
__device__ int   g_esrc[TEDGE * NEDGE];

#define F_RELU  1
#define F_ACCUM 2

struct GemmMap {
    long long aoff[TEDGE];
    long long boff[TEDGE];
    long long biasoff[TEDGE];
    long long coff[TEDGE];
    int       flags[TEDGE];
};

// Arch-feature gate: tcgen05 only exists in the compute_103a / compute_100a passes.
#if defined(__CUDA_ARCH__) && (defined(__CUDA_ARCH_FEAT_SM103_ALL) || defined(__CUDA_ARCH_FEAT_SM100_ALL))
#define USE_TCGEN05 1
#else
#define USE_TCGEN05 0
#endif

// ---------------- common helpers ----------------
__device__ __forceinline__ void splitf(float f, uint32_t& hi, uint32_t& lo) {
    uint32_t h = __float_as_uint(f) & 0xFFFFE000u;   // exact tf32 value
    hi = h;
    lo = __float_as_uint(f - __uint_as_float(h));    // exact residual
}

// ---- fallback (mma.sync) smem geometry ----
#define ASTR 36
#define BSTR 132
#define FB_AH 0
#define FB_AL (128 * ASTR)
#define FB_BH (2 * 128 * ASTR)
#define FB_BL (2 * 128 * ASTR + 32 * BSTR)
#define FB_WORDS (2 * 128 * ASTR + 2 * 32 * BSTR)   // 17664 words / buffer
#define FB_BYTES (2 * FB_WORDS * 4)                 // 141,312 B (>= TC's 133,120)

#if USE_TCGEN05
// ---------------- tcgen05 helpers (compiled only for *a* targets) ----------------
__device__ __forceinline__ uint32_t smem_u32ptr(const void* p) {
    uint32_t a;
    asm("{ .reg .u64 t; cvta.to.shared.u64 t, %1; cvt.u32.u64 %0, t; }" : "=r"(a) : "l"(p));
    return a;
}
__device__ __forceinline__ uint32_t elect1() {
    uint32_t r;
    asm volatile("{ .reg .pred p; elect.sync _|p, 0xFFFFFFFF; selp.b32 %0,1,0,p; }" : "=r"(r));
    return r;
}
__device__ __forceinline__ void mbar_init(uint32_t a, uint32_t c) {
    asm volatile("mbarrier.init.shared.b64 [%0], %1;" :: "r"(a), "r"(c) : "memory");
}
__device__ __forceinline__ void mbar_wait(uint32_t a, uint32_t ph) {
    asm volatile(
        "{ .reg .pred P;\n"
        "WL%=: mbarrier.try_wait.parity.acquire.cta.shared::cta.b64 P, [%0], %1, 0x989680;\n"
        "@P bra WD%=;\n"
        "bra WL%=;\n"
        "WD%=: }"
        :: "r"(a), "r"(ph) : "memory");
}
#define TC_ALLOC(slot, n) \
    asm volatile("tcgen05.alloc.cta_group::1.sync.aligned.shared::cta.b32 [%0], %1;" \
                 :: "r"(slot), "r"((uint32_t)(n)) : "memory")
#define TC_RELQ() \
    asm volatile("tcgen05.relinquish_alloc_permit.cta_group::1.sync.aligned;")
#define TC_DEALLOC(t, n) \
    asm volatile("tcgen05.dealloc.cta_group::1.sync.aligned.b32 %0, %1;" :: "r"(t), "r"((uint32_t)(n)))
#define TC_COMMIT(mb) \
    asm volatile("tcgen05.commit.cta_group::1.mbarrier::arrive::one.shared::cluster.b64 [%0];" \
                 :: "r"(mb) : "memory")
#define TC_FENCE_AFTER()  asm volatile("tcgen05.fence::after_thread_sync;" ::: "memory")
#define TC_FENCE_BEFORE() asm volatile("tcgen05.fence::before_thread_sync;" ::: "memory")
#define TC_WAIT_LD()      asm volatile("tcgen05.wait::ld.sync.aligned;" ::: "memory")
#define FENCE_PROXY()     asm volatile("fence.proxy.async.shared::cta;" ::: "memory")
#define SMEM_SWZ(off) ((off) ^ (((off) >> 3) & 0x70))

static __device__ __forceinline__ uint64_t make_desc(uint32_t addr) {
    const uint64_t base =
        (uint64_t(2) << 61) | (uint64_t(1) << 46) | (uint64_t(64) << 32) | (uint64_t(1) << 16);
    return base | ((uint64_t)(addr >> 4) & 0x3FFF);
}
// idesc: dtype=F32(1 @ [4:5]), atype=btype=TF32(2), N/8 @ [17:22], M/16 @ [24:28]
#define TC_IDESC ((1u << 4) | (2u << 7) | (2u << 10) | ((128u / 8u) << 17) | ((128u / 16u) << 24))

__device__ __forceinline__ void tc_mma_tf32(uint32_t d, uint64_t a, uint64_t b, uint32_t en) {
    asm volatile(
        "{\n\t"
        ".reg .pred p;\n\t"
        "setp.ne.u32 p, %4, 0;\n\t"
        "tcgen05.mma.cta_group::1.kind::tf32 [%0], %1, %2, %3, {%5,%5,%5,%5}, p;\n\t"
        "}"
        :: "r"(d), "l"(a), "l"(b), "r"(TC_IDESC), "r"(en), "r"(0u)
        : "memory");
}
// smem plane byte offsets within a TC buffer
#define P_AH 0
#define P_AL 16384
#define P_BH 32768
#define P_BL 49152
#endif  // USE_TCGEN05

#if !USE_TCGEN05
__device__ __forceinline__ void mma_tf32(float* d, const uint32_t* a, const uint32_t* b) {
    asm volatile(
        "mma.sync.aligned.m16n8k8.row.col.f32.tf32.tf32.f32 "
        "{%0,%1,%2,%3}, {%4,%5,%6,%7}, {%8,%9}, {%0,%1,%2,%3};"
        : "+f"(d[0]), "+f"(d[1]), "+f"(d[2]), "+f"(d[3])
        : "r"(a[0]), "r"(a[1]), "r"(a[2]), "r"(a[3]), "r"(b[0]), "r"(b[1]));
}
#endif

// ---------------- batched GEMM: C[z] = op(A[z] @ B[z] + bias) ----------------
__global__ __launch_bounds__(512, 1)
void gemm_kernel(const float* __restrict__ Ab, const float* __restrict__ Bb,
                 const float* __restrict__ biasb, float* __restrict__ Cb,
                 int M, int N, int K, GemmMap map)
{
    extern __shared__ uint32_t dsm[];

    const int z = blockIdx.z;
    const float* __restrict__ A    = Ab    + map.aoff[z];
    const float* __restrict__ B    = Bb    + map.boff[z];
    const float* __restrict__ bias = biasb + map.biasoff[z];
    float* __restrict__       C    = Cb    + map.coff[z];
    const int flags = map.flags[z];

    const int tid  = threadIdx.x;
    const int warp = tid >> 5;
    const int lane = tid & 31;
    const int bm = blockIdx.y << 7;
    const int bn = blockIdx.x << 7;
    const int nk = K >> 5;

#if USE_TCGEN05
    // =================== tcgen05 path ===================
    uint32_t sbase = smem_u32ptr(dsm);
    uint32_t tslot = sbase;
    uint32_t mb0 = sbase + 8, mb1 = sbase + 16;
    uint32_t abase = (sbase + 1023) & ~1023u;
    char* smc = (char*)dsm + (abase - sbase);

    if (tid == 0) { mbar_init(mb0, 1); mbar_init(mb1, 1); }
    if (warp == 0) { TC_ALLOC(tslot, 128); TC_RELQ(); }
    __syncthreads();
    uint32_t tmem;
    asm volatile("ld.shared.b32 %0, [%1];" : "=r"(tmem) : "r"(tslot));

    int ph0 = 0, ph1 = 0;

    for (int kt = 0; kt < nk; kt++) {
        const int b = kt & 1;
        const uint32_t bufb = abase + (b << 16);
        char* bufc = smc + (b << 16);
        if (kt >= 2) {
            if (b == 0) { mbar_wait(mb0, ph0); ph0 ^= 1; }
            else        { mbar_wait(mb1, ph1); ph1 ^= 1; }
        }

        // A tile: [m 0..127][k 0..31], K-major 128B rows, SW128
#pragma unroll
        for (int i = 0; i < 2; i++) {
            int id = tid + (i << 9);
            int row = id >> 3, q = id & 7;
            int gr = bm + row;
            float4 v = make_float4(0.f, 0.f, 0.f, 0.f);
            if (gr < M) v = *(const float4*)(A + (long long)gr * K + (kt << 5) + (q << 2));
            uint4 h, l;
            splitf(v.x, h.x, l.x); splitf(v.y, h.y, l.y);
            splitf(v.z, h.z, l.z); splitf(v.w, h.w, l.w);
            uint32_t sw = SMEM_SWZ((row << 7) + (q << 4));
            *(uint4*)(bufc + P_AH + sw) = h;
            *(uint4*)(bufc + P_AL + sw) = l;
        }
        // B tile: rows = n (128), cols = k (32); transpose from [K,N]
#pragma unroll
        for (int i = 0; i < 2; i++) {
            int id = tid + (i << 9);
            int n = id & 127, q = id >> 7;
            const float* bp = B + (long long)((kt << 5) + (q << 2)) * N + bn + n;
            float v0 = __ldg(bp);
            float v1 = __ldg(bp + N);
            float v2 = __ldg(bp + 2 * N);
            float v3 = __ldg(bp + 3 * N);
            uint4 h, l;
            splitf(v0, h.x, l.x); splitf(v1, h.y, l.y);
            splitf(v2, h.z, l.z); splitf(v3, h.w, l.w);
            uint32_t sw = SMEM_SWZ((n << 7) + (q << 4));
            *(uint4*)(bufc + P_BH + sw) = h;
            *(uint4*)(bufc + P_BL + sw) = l;
        }
        FENCE_PROXY();
        __syncthreads();

        if (warp == 0) {
            if (elect1()) {
                uint64_t dah = make_desc(bufb + P_AH);
                uint64_t dal = make_desc(bufb + P_AL);
                uint64_t dbh = make_desc(bufb + P_BH);
                uint64_t dbl = make_desc(bufb + P_BL);
                uint32_t en = (kt > 0) ? 1u : 0u;
#pragma unroll
                for (int ks = 0; ks < 4; ks++) {
                    uint64_t o = (uint64_t)(ks * 2);
                    tc_mma_tf32(tmem, dah + o, dbh + o, en); en = 1u;
                    tc_mma_tf32(tmem, dah + o, dbl + o, 1u);
                    tc_mma_tf32(tmem, dal + o, dbh + o, 1u);
                }
                TC_COMMIT(b ? mb1 : mb0);
            }
        }
    }

    {
        int lb = (nk - 1) & 1;
        mbar_wait(lb ? mb1 : mb0, lb ? ph1 : ph0);
    }
    TC_FENCE_AFTER();

    // epilogue: warp w -> rows (w&3)*32 (its subpartition), cols (w>>2)*32
    {
        int wc = warp >> 2;
        uint32_t r[32];
        asm volatile(
            "tcgen05.ld.sync.aligned.32x32b.x32.b32 "
            "{%0, %1, %2, %3, %4, %5, %6, %7, "
            " %8, %9, %10, %11, %12, %13, %14, %15, "
            " %16, %17, %18, %19, %20, %21, %22, %23, "
            " %24, %25, %26, %27, %28, %29, %30, %31}, [%32];"
            : "=r"(r[0]),  "=r"(r[1]),  "=r"(r[2]),  "=r"(r[3]),
              "=r"(r[4]),  "=r"(r[5]),  "=r"(r[6]),  "=r"(r[7]),
              "=r"(r[8]),  "=r"(r[9]),  "=r"(r[10]), "=r"(r[11]),
              "=r"(r[12]), "=r"(r[13]), "=r"(r[14]), "=r"(r[15]),
              "=r"(r[16]), "=r"(r[17]), "=r"(r[18]), "=r"(r[19]),
              "=r"(r[20]), "=r"(r[21]), "=r"(r[22]), "=r"(r[23]),
              "=r"(r[24]), "=r"(r[25]), "=r"(r[26]), "=r"(r[27]),
              "=r"(r[28]), "=r"(r[29]), "=r"(r[30]), "=r"(r[31])
            : "r"(tmem + (wc << 5)));
        TC_WAIT_LD();

        int row = bm + ((warp & 3) << 5) + lane;
        if (row < M) {
            int colb = bn + (wc << 5);
            float* cp = C + (long long)row * N + colb;
#pragma unroll
            for (int c4 = 0; c4 < 8; c4++) {
                float4 bb = *(const float4*)(bias + colb + (c4 << 2));
                float4 v;
                v.x = __uint_as_float(r[c4 * 4 + 0]) + bb.x;
                v.y = __uint_as_float(r[c4 * 4 + 1]) + bb.y;
                v.z = __uint_as_float(r[c4 * 4 + 2]) + bb.z;
                v.w = __uint_as_float(r[c4 * 4 + 3]) + bb.w;
                if (flags & F_ACCUM) {
                    float4 o = *(const float4*)(cp + (c4 << 2));
                    v.x += o.x; v.y += o.y; v.z += o.z; v.w += o.w;
                }
                if (flags & F_RELU) {
                    v.x = fmaxf(v.x, 0.f); v.y = fmaxf(v.y, 0.f);
                    v.z = fmaxf(v.z, 0.f); v.w = fmaxf(v.w, 0.f);
                }
                *(float4*)(cp + (c4 << 2)) = v;
            }
        }
        TC_FENCE_BEFORE();
    }
    __syncthreads();
    if (warp == 0) TC_DEALLOC(tmem, 128);

#else
    // =================== fallback: 3xTF32 mma.sync, 16 warps ===================
    const int g = lane >> 2;            // group 0..7
    const int t = lane & 3;             // quad 0..3
    const int wm = (warp & 3) << 5;     // warp m offset: 0/32/64/96
    const int wn = (warp >> 2) << 5;    // warp n offset: 0/32/64/96

    float acc[2][4][4];
#pragma unroll
    for (int mi = 0; mi < 2; mi++)
#pragma unroll
        for (int ni = 0; ni < 4; ni++)
#pragma unroll
            for (int q = 0; q < 4; q++) acc[mi][ni][q] = 0.f;

    float4 aR[2], bR[2];

    // staging: A: id -> row=id>>3 (0..127), kq=id&7 ; B: row=id>>5 (0..31), cq=id&31
#pragma unroll
    for (int i = 0; i < 2; i++) {
        int id = tid + (i << 9);
        int ar = id >> 3, akq = id & 7;
        int gr = bm + ar;
        if (gr < M) aR[i] = *(const float4*)(A + (long long)gr * K + (akq << 2));
        else        aR[i] = make_float4(0.f, 0.f, 0.f, 0.f);
        int br = id >> 5, bcq = id & 31;
        bR[i] = *(const float4*)(B + (long long)br * N + bn + (bcq << 2));
    }
#pragma unroll
    for (int i = 0; i < 2; i++) {
        int id = tid + (i << 9);
        int ar = id >> 3, akq = id & 7;
        uint4 h, l;
        splitf(aR[i].x, h.x, l.x); splitf(aR[i].y, h.y, l.y);
        splitf(aR[i].z, h.z, l.z); splitf(aR[i].w, h.w, l.w);
        *(uint4*)&dsm[FB_AH + ar * ASTR + (akq << 2)] = h;
        *(uint4*)&dsm[FB_AL + ar * ASTR + (akq << 2)] = l;
        int br = id >> 5, bcq = id & 31;
        uint4 bh, bl;
        splitf(bR[i].x, bh.x, bl.x); splitf(bR[i].y, bh.y, bl.y);
        splitf(bR[i].z, bh.z, bl.z); splitf(bR[i].w, bh.w, bl.w);
        *(uint4*)&dsm[FB_BH + br * BSTR + (bcq << 2)] = bh;
        *(uint4*)&dsm[FB_BL + br * BSTR + (bcq << 2)] = bl;
    }
    __syncthreads();

    const int aBase = (wm + g) * ASTR + t;
    const int bBase = t * BSTR + wn + g;
    int bufOff = 0;

    for (int kt = 0; kt < nk; kt++) {
        if (kt + 1 < nk) {
            const float* An = A + ((kt + 1) << 5);
            const float* Bn = B + (long long)((kt + 1) << 5) * N;
#pragma unroll
            for (int i = 0; i < 2; i++) {
                int id = tid + (i << 9);
                int ar = id >> 3, akq = id & 7;
                int gr = bm + ar;
                if (gr < M) aR[i] = *(const float4*)(An + (long long)gr * K + (akq << 2));
                else        aR[i] = make_float4(0.f, 0.f, 0.f, 0.f);
                int br = id >> 5, bcq = id & 31;
                bR[i] = *(const float4*)(Bn + (long long)br * N + bn + (bcq << 2));
            }
        }

        const uint32_t* AsH = dsm + bufOff + FB_AH;
        const uint32_t* AsL = dsm + bufOff + FB_AL;
        const uint32_t* BsH = dsm + bufOff + FB_BH;
        const uint32_t* BsL = dsm + bufOff + FB_BL;
#pragma unroll
        for (int ks = 0; ks < 4; ks++) {
            uint32_t afh[2][4], afl[2][4], bfh[4][2], bfl[4][2];
#pragma unroll
            for (int mi = 0; mi < 2; mi++) {
                int p = aBase + (mi << 4) * ASTR + (ks << 3);
                afh[mi][0] = AsH[p];                afl[mi][0] = AsL[p];
                afh[mi][1] = AsH[p + 8 * ASTR];     afl[mi][1] = AsL[p + 8 * ASTR];
                afh[mi][2] = AsH[p + 4];            afl[mi][2] = AsL[p + 4];
                afh[mi][3] = AsH[p + 8 * ASTR + 4]; afl[mi][3] = AsL[p + 8 * ASTR + 4];
            }
#pragma unroll
            for (int ni = 0; ni < 4; ni++) {
                int p = bBase + (ks << 3) * BSTR + (ni << 3);
                bfh[ni][0] = BsH[p];                bfl[ni][0] = BsL[p];
                bfh[ni][1] = BsH[p + 4 * BSTR];     bfl[ni][1] = BsL[p + 4 * BSTR];
            }
#pragma unroll
            for (int mi = 0; mi < 2; mi++)
#pragma unroll
                for (int ni = 0; ni < 4; ni++) {
                    mma_tf32(acc[mi][ni], afh[mi], bfh[ni]);
                    mma_tf32(acc[mi][ni], afh[mi], bfl[ni]);
                    mma_tf32(acc[mi][ni], afl[mi], bfh[ni]);
                }
        }

        if (kt + 1 < nk) {
            int nOff = bufOff ^ FB_WORDS;
#pragma unroll
            for (int i = 0; i < 2; i++) {
                int id = tid + (i << 9);
                int ar = id >> 3, akq = id & 7;
                uint4 h, l;
                splitf(aR[i].x, h.x, l.x); splitf(aR[i].y, h.y, l.y);
                splitf(aR[i].z, h.z, l.z); splitf(aR[i].w, h.w, l.w);
                *(uint4*)&dsm[nOff + FB_AH + ar * ASTR + (akq << 2)] = h;
                *(uint4*)&dsm[nOff + FB_AL + ar * ASTR + (akq << 2)] = l;
                int br = id >> 5, bcq = id & 31;
                uint4 bh, bl;
                splitf(bR[i].x, bh.x, bl.x); splitf(bR[i].y, bh.y, bl.y);
                splitf(bR[i].z, bh.z, bl.z); splitf(bR[i].w, bh.w, bl.w);
                *(uint4*)&dsm[nOff + FB_BH + br * BSTR + (bcq << 2)] = bh;
                *(uint4*)&dsm[nOff + FB_BL + br * BSTR + (bcq << 2)] = bl;
            }
        }
        __syncthreads();
        bufOff ^= FB_WORDS;
    }

    // epilogue
    float2 bia[4];
#pragma unroll
    for (int ni = 0; ni < 4; ni++)
        bia[ni] = *(const float2*)(bias + bn + wn + (ni << 3) + (t << 1));

#pragma unroll
    for (int mi = 0; mi < 2; mi++) {
        int r0 = bm + wm + (mi << 4) + g;
        int r1 = r0 + 8;
#pragma unroll
        for (int ni = 0; ni < 4; ni++) {
            int col = bn + wn + (ni << 3) + (t << 1);
#pragma unroll
            for (int h = 0; h < 2; h++) {
                int r = h ? r1 : r0;
                if (r >= M) continue;
                float2 v;
                v.x = acc[mi][ni][h ? 2 : 0] + bia[ni].x;
                v.y = acc[mi][ni][h ? 3 : 1] + bia[ni].y;
                float* cp = C + (long long)r * N + col;
                if (flags & F_ACCUM) {
                    float2 o = *(const float2*)cp;
                    v.x += o.x; v.y += o.y;
                }
                if (flags & F_RELU) {
                    v.x = fmaxf(v.x, 0.f);
                    v.y = fmaxf(v.y, 0.f);
                }
                *(float2*)cp = v;
            }
        }
    }
#endif
}

// ---------------- CSR build: count -> scan -> fill ----------------
__global__ void count_kernel(const int* __restrict__ edges, int* __restrict__ cnt)
{
    int idx = blockIdx.x * blockDim.x + threadIdx.x;
    if (idx >= TEDGE * NEDGE) return;
    int t = idx / NEDGE;
    int e = idx - t * NEDGE;
    int dn = __ldg(edges + (long long)t * 2 * NEDGE + NEDGE + e);
    atomicAdd(&cnt[t * NNODES + dn], 1);
}

__global__ void scan_kernel(const int* __restrict__ cnt, int* __restrict__ indptr,
                            int* __restrict__ fill)
{
    __shared__ int sh[1024];
    __shared__ int run;
    int t = blockIdx.x;
    if (threadIdx.x == 0) { run = 0; indptr[t * (NNODES + 1)] = 0; }
    __syncthreads();
    const int* c = cnt + t * NNODES;
    int* ip = indptr + t * (NNODES + 1);
    for (int base = 0; base < NNODES; base += 1024) {
        int i = base + threadIdx.x;
        int v = (i < NNODES) ? c[i] : 0;
        sh[threadIdx.x] = v;
        __syncthreads();
        for (int off = 1; off < 1024; off <<= 1) {
            int x = (threadIdx.x >= off) ? sh[threadIdx.x - off] : 0;
            __syncthreads();
            sh[threadIdx.x] += x;
            __syncthreads();
        }
        if (i < NNODES) ip[i + 1] = run + sh[threadIdx.x];
        __syncthreads();
        if (threadIdx.x == 0) run += sh[1023];
        __syncthreads();
    }
    for (int i = threadIdx.x; i < NNODES; i += 1024)
        fill[t * NNODES + i] = ip[i];
}

__global__ void fill_kernel(const int* __restrict__ edges, int* __restrict__ fill,
                            int* __restrict__ esrc)
{
    int idx = blockIdx.x * blockDim.x + threadIdx.x;
    if (idx >= TEDGE * NEDGE) return;
    int t = idx / NEDGE;
    int e = idx - t * NEDGE;
    const int* base = edges + (long long)t * 2 * NEDGE;
    int sn = __ldg(base + e);
    int dn = __ldg(base + NEDGE + e);
    int pos = atomicAdd(&fill[t * NNODES + dn], 1);
    esrc[t * NEDGE + pos] = sn;
}

// ---------------- gather: 4 warps per (t,node); each warp owns 128 features ----
__global__ void gather_kernel(const float* __restrict__ h, float* __restrict__ agg6,
                              const int* __restrict__ indptr, const int* __restrict__ esrc)
{
    int gw   = (blockIdx.x * blockDim.x + threadIdx.x) >> 5;
    int lane = threadIdx.x & 31;
    if (gw >= TEDGE * NNODES * 4) return;
    int part = gw & 3;
    int seg  = gw >> 2;
    int t = seg / NNODES;
    int node = seg - t * NNODES;
    int beg = __ldg(indptr + t * (NNODES + 1) + node);
    int end = __ldg(indptr + t * (NNODES + 1) + node + 1);
    int col = (part << 5) + lane;   // float4 index 0..127

    const float4* drow = (const float4*)(h + ((long long)c_dstT[t] * NNODES + node) * HDIM);
    float4 a = __ldg(drow + col);

    const float* hsrc = h + (long long)c_srcT[t] * NNODES * HDIM;
    const int* el = esrc + (long long)t * NEDGE;

    int j = beg;
    for (; j + 3 < end; j += 4) {
        int s0 = __ldg(el + j), s1 = __ldg(el + j + 1);
        int s2 = __ldg(el + j + 2), s3 = __ldg(el + j + 3);
        float4 p0 = __ldg((const float4*)(hsrc + (long long)s0 * HDIM) + col);
        float4 p1 = __ldg((const float4*)(hsrc + (long long)s1 * HDIM) + col);
        float4 p2 = __ldg((const float4*)(hsrc + (long long)s2 * HDIM) + col);
        float4 p3 = __ldg((const float4*)(hsrc + (long long)s3 * HDIM) + col);
        a.x += (p0.x + p1.x) + (p2.x + p3.x);
        a.y += (p0.y + p1.y) + (p2.y + p3.y);
        a.z += (p0.z + p1.z) + (p2.z + p3.z);
        a.w += (p0.w + p1.w) + (p2.w + p3.w);
    }
    for (; j < end; j++) {
        int s0 = __ldg(el + j);
        float4 p0 = __ldg((const float4*)(hsrc + (long long)s0 * HDIM) + col);
        a.x += p0.x; a.y += p0.y; a.z += p0.z; a.w += p0.w;
    }

    ((float4*)(agg6 + ((long long)t * NNODES + node) * HDIM))[col] = a;
}

// ---------------- output head ----------------
__global__ void head_kernel(const float* __restrict__ h0, const float* __restrict__ Wout,
                            const float* __restrict__ bout, float* __restrict__ out)
{
    int node = (blockIdx.x * blockDim.x + threadIdx.x) >> 5;
    int lane = threadIdx.x & 31;
    if (node >= NNODES) return;
    const float4* row = (const float4*)(h0 + (long long)node * HDIM);
    const float4* w4  = (const float4*)Wout;
    float s = 0.f;
#pragma unroll
    for (int k = 0; k < 4; k++) {
        float4 a = row[lane + (k << 5)];
        float4 w = __ldg(w4 + lane + (k << 5));
        s += a.x * w.x + a.y * w.y + a.z * w.z + a.w * w.w;
    }
#pragma unroll
    for (int off = 16; off; off >>= 1) s += __shfl_down_sync(0xffffffffu, s, off);
    if (lane == 0) out[node] = s + bout[0];
}

// ---------------- host launch ----------------
extern "C" void kernel_launch(void* const* d_in, const int* in_sizes, int n_in,
                              void* d_out, int out_size)
{
    const float *x = nullptr, *Win = nullptr, *bin = nullptr;
    const float *W1 = nullptr, *b1 = nullptr, *W2 = nullptr, *b2 = nullptr;
    const float *Wout = nullptr, *bout = nullptr;
    const int* edges = nullptr;

    for (int i = 0; i < n_in; i++) {
        int s = in_sizes[i];
        const void* p = d_in[i];
        switch (s) {
            case 6400000: x    = (const float*)p; break;
            case 163840:  Win  = (const float*)p; break;
            case 2560:    bin  = (const float*)p; break;
            case 3145728: if (!W1) W1 = (const float*)p; else W2 = (const float*)p; break;
            case 6144:    if (!b1) b1 = (const float*)p; else b2 = (const float*)p; break;
            case 512:     Wout = (const float*)p; break;
            case 1:       bout = (const float*)p; break;
            case 1920000: edges = (const int*)p; break;
        }
    }

    static bool attr_done = false;
    if (!attr_done) {
        cudaFuncSetAttribute(gemm_kernel,
                             cudaFuncAttributeMaxDynamicSharedMemorySize, FB_BYTES);
        attr_done = true;
    }

    float *hA, *hB, *agg6, *tmp6;
    int *cnt, *fillp, *indptr, *esrc;
    cudaGetSymbolAddress((void**)&hA,     g_hA);
    cudaGetSymbolAddress((void**)&hB,     g_hB);
    cudaGetSymbolAddress((void**)&agg6,   g_agg6);
    cudaGetSymbolAddress((void**)&tmp6,   g_tmp6);
    cudaGetSymbolAddress((void**)&cnt,    g_cnt);
    cudaGetSymbolAddress((void**)&fillp,  g_fill);
    cudaGetSymbolAddress((void**)&indptr, g_indptr);
    cudaGetSymbolAddress((void**)&esrc,   g_esrc);

    const int gy = (NNODES + 127) / 128;   // 157
    const int dstT[TEDGE] = {1, 0, 2, 3, 0, 4};

    // 0) CSR build (edge structure is layer-independent)
    cudaMemsetAsync(cnt, 0, (size_t)TEDGE * NNODES * sizeof(int));
    count_kernel<<<(TEDGE * NEDGE + 255) / 256, 256>>>(edges, cnt);
    scan_kernel<<<TEDGE, 1024>>>(cnt, indptr, fillp);
    fill_kernel<<<(TEDGE * NEDGE + 255) / 256, 256>>>(edges, fillp, esrc);

    // 1) input projection: h = relu(x @ W_in + b_in), batched over 5 types (K=64)
    {
        GemmMap m = {};
        for (int t = 0; t < NTYPES; t++) {
            m.aoff[t]    = (long long)t * NNODES * FIN;
            m.boff[t]    = (long long)t * FIN * HDIM;
            m.biasoff[t] = (long long)t * HDIM;
            m.coff[t]    = (long long)t * NH;
            m.flags[t]   = F_RELU;
        }
        gemm_kernel<<<dim3(HDIM / 128, gy, NTYPES), 512, FB_BYTES>>>(
            x, Win, bin, hA, NNODES, HDIM, FIN, m);
    }

    float* hcur = hA;
    float* hnext = hB;

    for (int l = 0; l < 2; l++) {
        // 2a+2b) fused gather: agg6[t] = h[dstT[t]] + segment_sum(h[srcT[t]])
        {
            int warps = TEDGE * NNODES * 4;           // 480000
            int blocks = (warps + 7) / 8;
            gather_kernel<<<blocks, 256>>>(hcur, agg6, indptr, esrc);
        }
        // 2c) GEMM1: tmp6[t] = relu(agg6[t] @ W1[l,t] + b1[l,t])
        {
            GemmMap m = {};
            for (int t = 0; t < TEDGE; t++) {
                m.aoff[t]    = (long long)t * NH;
                m.boff[t]    = ((long long)l * TEDGE + t) * HDIM * HDIM;
                m.biasoff[t] = ((long long)l * TEDGE + t) * HDIM;
                m.coff[t]    = (long long)t * NH;
                m.flags[t]   = F_RELU;
            }
            gemm_kernel<<<dim3(HDIM / 128, gy, TEDGE), 512, FB_BYTES>>>(
                agg6, W1, b1, tmp6, NNODES, HDIM, HDIM, m);
        }
        // 2d) GEMM2 group 1: t in {0,1,2,3,5}; t=1 (dst 0) stays raw for t=4 accum
        {
            GemmMap m = {};
            const int zs[5] = {0, 1, 2, 3, 5};
            for (int zi = 0; zi < 5; zi++) {
                int t = zs[zi];
                m.aoff[zi]    = (long long)t * NH;
                m.boff[zi]    = ((long long)l * TEDGE + t) * HDIM * HDIM;
                m.biasoff[zi] = ((long long)l * TEDGE + t) * HDIM;
                m.coff[zi]    = (long long)dstT[t] * NH;
                m.flags[zi]   = (t == 1) ? 0 : F_RELU;
            }
            gemm_kernel<<<dim3(HDIM / 128, gy, 5), 512, FB_BYTES>>>(
                tmp6, W2, b2, hnext, NNODES, HDIM, HDIM, m);
        }
        // 2e) GEMM2 group 2: t=4 accumulates into dst 0, then relu
        {
            GemmMap m = {};
            m.aoff[0]    = (long long)4 * NH;
            m.boff[0]    = ((long long)l * TEDGE + 4) * HDIM * HDIM;
            m.biasoff[0] = ((long long)l * TEDGE + 4) * HDIM;
            m.coff[0]    = 0;
            m.flags[0]   = F_ACCUM | F_RELU;
            gemm_kernel<<<dim3(HDIM / 128, gy, 1), 512, FB_BYTES>>>(
                tmp6, W2, b2, hnext, NNODES, HDIM, HDIM, m);
        }
        float* tswap = hcur; hcur = hnext; hnext = tswap;
    }

    // 3) output head on type 0
    {
        int blocks = (NNODES + 7) / 8;
        head_kernel<<<blocks, 256>>>(hcur, Wout, bout, (float*)d_out);
    }
    (void)out_size; (void)n_in;
}

// round 12
// speedup vs baseline: 3.3223x; 1.2684x over previous
#include <cuda_runtime.h>
#include <cstdint>

// ---------------- problem constants ----------------
#define NNODES 20000
#define FIN    64
#define HDIM   512
#define NTYPES 5
#define TEDGE  6
#define NEDGE  160000
#define NH     (NNODES * HDIM)

// EDGE_TYPES = ((4,1),(1,0),(0,2),(2,3),(3,0),(1,4))
__constant__ int c_srcT[TEDGE] = {4, 1, 0, 2, 3, 1};
__constant__ int c_dstT[TEDGE] = {1, 0, 2, 3, 0, 4};

// ---------------- device scratch (no allocs allowed) ----------------
__device__ float g_hA[NTYPES * NH];
__device__ float g_hB[NTYPES * NH];
__device__ float g_agg6[TEDGE * NH];
__device__ float g_tmp6[TEDGE * NH];
__device__ int   g_cnt[TEDGE * NNODES];
__device__ int   g_fill[TEDGE * NNODES];
__device__ int   g_indptr[TEDGE * (NNODES + 1)];
__device__ int   g_esrc[TEDGE * NEDGE];

#define F_RELU  1
#define F_BIAS2 2

// Per-z GEMM description. Optional second K segment (aoff2/boff2, nk2 k-tiles)
// concatenates onto K: D = A1@B1 + A2@B2 (+bias (+bias2)).
struct GemmMap {
    long long aoff[TEDGE],  aoff2[TEDGE];
    long long boff[TEDGE],  boff2[TEDGE];
    long long biasoff[TEDGE], biasoff2[TEDGE];
    long long coff[TEDGE];
    int       nk2[TEDGE];
    int       flags[TEDGE];
};

// Arch-feature gate: tcgen05 only exists in the compute_103a / compute_100a passes.
#if defined(__CUDA_ARCH__) && (defined(__CUDA_ARCH_FEAT_SM103_ALL) || defined(__CUDA_ARCH_FEAT_SM100_ALL))
#define USE_TCGEN05 1
#else
#define USE_TCGEN05 0
#endif

__device__ __forceinline__ void splitf(float f, uint32_t& hi, uint32_t& lo) {
    uint32_t h = __float_as_uint(f) & 0xFFFFE000u;   // exact tf32 value
    hi = h;
    lo = __float_as_uint(f - __uint_as_float(h));    // exact residual
}

// smem planes within one buffer: A (128x32) hi/lo = 16KB each, B (256x32) hi/lo = 32KB each
#define P_AH 0
#define P_AL 16384
#define P_BH 32768
#define P_BL 65536
#define BUF_BYTES 98304
#define SMEM_BYTES (2 * BUF_BYTES + 2048)   // 198,656 B

#if USE_TCGEN05
// ---------------- tcgen05 helpers (compiled only for *a* targets) ----------------
__device__ __forceinline__ uint32_t smem_u32ptr(const void* p) {
    uint32_t a;
    asm("{ .reg .u64 t; cvta.to.shared.u64 t, %1; cvt.u32.u64 %0, t; }" : "=r"(a) : "l"(p));
    return a;
}
__device__ __forceinline__ uint32_t elect1() {
    uint32_t r;
    asm volatile("{ .reg .pred p; elect.sync _|p, 0xFFFFFFFF; selp.b32 %0,1,0,p; }" : "=r"(r));
    return r;
}
__device__ __forceinline__ void mbar_init(uint32_t a, uint32_t c) {
    asm volatile("mbarrier.init.shared.b64 [%0], %1;" :: "r"(a), "r"(c) : "memory");
}
__device__ __forceinline__ void mbar_wait(uint32_t a, uint32_t ph) {
    asm volatile(
        "{ .reg .pred P;\n"
        "WL%=: mbarrier.try_wait.parity.acquire.cta.shared::cta.b64 P, [%0], %1, 0x989680;\n"
        "@P bra WD%=;\n"
        "bra WL%=;\n"
        "WD%=: }"
        :: "r"(a), "r"(ph) : "memory");
}
#define TC_ALLOC(slot, n) \
    asm volatile("tcgen05.alloc.cta_group::1.sync.aligned.shared::cta.b32 [%0], %1;" \
                 :: "r"(slot), "r"((uint32_t)(n)) : "memory")
#define TC_RELQ() \
    asm volatile("tcgen05.relinquish_alloc_permit.cta_group::1.sync.aligned;")
#define TC_DEALLOC(t, n) \
    asm volatile("tcgen05.dealloc.cta_group::1.sync.aligned.b32 %0, %1;" :: "r"(t), "r"((uint32_t)(n)))
#define TC_COMMIT(mb) \
    asm volatile("tcgen05.commit.cta_group::1.mbarrier::arrive::one.shared::cluster.b64 [%0];" \
                 :: "r"(mb) : "memory")
#define TC_FENCE_AFTER()  asm volatile("tcgen05.fence::after_thread_sync;" ::: "memory")
#define TC_FENCE_BEFORE() asm volatile("tcgen05.fence::before_thread_sync;" ::: "memory")
#define TC_WAIT_LD()      asm volatile("tcgen05.wait::ld.sync.aligned;" ::: "memory")
#define FENCE_PROXY()     asm volatile("fence.proxy.async.shared::cta;" ::: "memory")
#define SMEM_SWZ(off) ((off) ^ (((off) >> 3) & 0x70))

static __device__ __forceinline__ uint64_t make_desc(uint32_t addr) {
    const uint64_t base =
        (uint64_t(2) << 61) | (uint64_t(1) << 46) | (uint64_t(64) << 32) | (uint64_t(1) << 16);
    return base | ((uint64_t)(addr >> 4) & 0x3FFF);
}
// idesc: dtype=F32(1 @ [4:5]), atype=btype=TF32(2), N=128 (N/8 @ [17:22]), M=128 (M/16 @ [24:28])
#define TC_IDESC ((1u << 4) | (2u << 7) | (2u << 10) | ((128u / 8u) << 17) | ((128u / 16u) << 24))

__device__ __forceinline__ void tc_mma_tf32(uint32_t d, uint64_t a, uint64_t b, uint32_t en) {
    asm volatile(
        "{\n\t"
        ".reg .pred p;\n\t"
        "setp.ne.u32 p, %4, 0;\n\t"
        "tcgen05.mma.cta_group::1.kind::tf32 [%0], %1, %2, %3, {%5,%5,%5,%5}, p;\n\t"
        "}"
        :: "r"(d), "l"(a), "l"(b), "r"(TC_IDESC), "r"(en), "r"(0u)
        : "memory");
}
#endif  // USE_TCGEN05

// ---------------- batched GEMM: C[z](M x 512) block = 128 x 256 per CTA ----------------
__global__ __launch_bounds__(512, 1)
void gemm_kernel(const float* __restrict__ Ab, const float* __restrict__ Bb,
                 const float* __restrict__ biasb, float* __restrict__ Cb,
                 int M, int N, int K, GemmMap map)
{
    extern __shared__ uint32_t dsm[];

    const int z = blockIdx.z;
    const float* __restrict__ A1    = Ab + map.aoff[z];
    const float* __restrict__ A2    = Ab + map.aoff2[z];
    const float* __restrict__ B1    = Bb + map.boff[z];
    const float* __restrict__ B2    = Bb + map.boff2[z];
    const float* __restrict__ bias  = biasb + map.biasoff[z];
    const float* __restrict__ bias2 = biasb + map.biasoff2[z];
    float* __restrict__       C     = Cb + map.coff[z];
    const int flags = map.flags[z];
    const int nk1 = K >> 5;
    const int nkt = nk1 + map.nk2[z];

    const int tid  = threadIdx.x;
    const int warp = tid >> 5;
    const int lane = tid & 31;
    const int bm = blockIdx.y << 7;
    const int bn = blockIdx.x << 8;      // 256-wide N block

#if USE_TCGEN05
    uint32_t sbase = smem_u32ptr(dsm);
    uint32_t tslot = sbase;
    uint32_t mb0 = sbase + 8, mb1 = sbase + 16;
    uint32_t abase = (sbase + 1023) & ~1023u;
    char* smc = (char*)dsm + (abase - sbase);

    if (tid == 0) { mbar_init(mb0, 1); mbar_init(mb1, 1); }
    if (warp == 0) { TC_ALLOC(tslot, 256); TC_RELQ(); }
    __syncthreads();
    uint32_t tmem;
    asm volatile("ld.shared.b32 %0, [%1];" : "=r"(tmem) : "r"(tslot));

    int ph0 = 0, ph1 = 0;

    for (int kt = 0; kt < nkt; kt++) {
        const int b = kt & 1;
        const uint32_t bufb = abase + b * BUF_BYTES;
        char* bufc = smc + b * BUF_BYTES;
        if (kt >= 2) {
            if (b == 0) { mbar_wait(mb0, ph0); ph0 ^= 1; }
            else        { mbar_wait(mb1, ph1); ph1 ^= 1; }
        }

        const float* Ax; const float* Bx; int kk;
        if (kt < nk1) { Ax = A1; Bx = B1; kk = kt; }
        else          { Ax = A2; Bx = B2; kk = kt - nk1; }

        // A tile: [m 0..127][k 0..31], K-major 128B rows, SW128
#pragma unroll
        for (int i = 0; i < 2; i++) {
            int id = tid + (i << 9);
            int row = id >> 3, q = id & 7;
            int gr = bm + row;
            float4 v = make_float4(0.f, 0.f, 0.f, 0.f);
            if (gr < M) v = *(const float4*)(Ax + (long long)gr * K + (kk << 5) + (q << 2));
            uint4 h, l;
            splitf(v.x, h.x, l.x); splitf(v.y, h.y, l.y);
            splitf(v.z, h.z, l.z); splitf(v.w, h.w, l.w);
            uint32_t sw = SMEM_SWZ((row << 7) + (q << 4));
            *(uint4*)(bufc + P_AH + sw) = h;
            *(uint4*)(bufc + P_AL + sw) = l;
        }
        // B tile: rows = n (256), cols = k (32); transpose from [K,N]
#pragma unroll
        for (int i = 0; i < 4; i++) {
            int id = tid + (i << 9);
            int n = id & 255, q = id >> 8;
            const float* bp = Bx + (long long)((kk << 5) + (q << 2)) * N + bn + n;
            float v0 = __ldg(bp);
            float v1 = __ldg(bp + N);
            float v2 = __ldg(bp + 2 * N);
            float v3 = __ldg(bp + 3 * N);
            uint4 h, l;
            splitf(v0, h.x, l.x); splitf(v1, h.y, l.y);
            splitf(v2, h.z, l.z); splitf(v3, h.w, l.w);
            uint32_t sw = SMEM_SWZ((n << 7) + (q << 4));
            *(uint4*)(bufc + P_BH + sw) = h;
            *(uint4*)(bufc + P_BL + sw) = l;
        }
        FENCE_PROXY();
        __syncthreads();

        if (warp == 0) {
            if (elect1()) {
                uint64_t dah  = make_desc(bufb + P_AH);
                uint64_t dal  = make_desc(bufb + P_AL);
                uint64_t dbh0 = make_desc(bufb + P_BH);
                uint64_t dbh1 = make_desc(bufb + P_BH + 16384);
                uint64_t dbl0 = make_desc(bufb + P_BL);
                uint64_t dbl1 = make_desc(bufb + P_BL + 16384);
#pragma unroll
                for (int ks = 0; ks < 4; ks++) {
                    uint64_t o = (uint64_t)(ks * 2);
                    uint32_t en0 = (kt == 0 && ks == 0) ? 0u : 1u;
                    // N half 0 -> D cols 0..127
                    tc_mma_tf32(tmem,       dah + o, dbh0 + o, en0);
                    tc_mma_tf32(tmem,       dah + o, dbl0 + o, 1u);
                    tc_mma_tf32(tmem,       dal + o, dbh0 + o, 1u);
                    // N half 1 -> D cols 128..255
                    tc_mma_tf32(tmem + 128, dah + o, dbh1 + o, en0);
                    tc_mma_tf32(tmem + 128, dah + o, dbl1 + o, 1u);
                    tc_mma_tf32(tmem + 128, dal + o, dbh1 + o, 1u);
                }
                TC_COMMIT(b ? mb1 : mb0);
            }
        }
    }

    {
        int lb = (nkt - 1) & 1;
        mbar_wait(lb ? mb1 : mb0, lb ? ph1 : ph0);
    }
    TC_FENCE_AFTER();

    // epilogue: warp w -> rows (w&3)*32 (its subpartition), cols (w>>2)*32 of each half
    {
        int wc = warp >> 2;
        int row = bm + ((warp & 3) << 5) + lane;
#pragma unroll
        for (int half = 0; half < 2; half++) {
            uint32_t r[32];
            asm volatile(
                "tcgen05.ld.sync.aligned.32x32b.x32.b32 "
                "{%0, %1, %2, %3, %4, %5, %6, %7, "
                " %8, %9, %10, %11, %12, %13, %14, %15, "
                " %16, %17, %18, %19, %20, %21, %22, %23, "
                " %24, %25, %26, %27, %28, %29, %30, %31}, [%32];"
                : "=r"(r[0]),  "=r"(r[1]),  "=r"(r[2]),  "=r"(r[3]),
                  "=r"(r[4]),  "=r"(r[5]),  "=r"(r[6]),  "=r"(r[7]),
                  "=r"(r[8]),  "=r"(r[9]),  "=r"(r[10]), "=r"(r[11]),
                  "=r"(r[12]), "=r"(r[13]), "=r"(r[14]), "=r"(r[15]),
                  "=r"(r[16]), "=r"(r[17]), "=r"(r[18]), "=r"(r[19]),
                  "=r"(r[20]), "=r"(r[21]), "=r"(r[22]), "=r"(r[23]),
                  "=r"(r[24]), "=r"(r[25]), "=r"(r[26]), "=r"(r[27]),
                  "=r"(r[28]), "=r"(r[29]), "=r"(r[30]), "=r"(r[31])
                : "r"(tmem + (half << 7) + (wc << 5)));
            TC_WAIT_LD();

            if (row < M) {
                int colb = bn + (half << 7) + (wc << 5);
                float* cp = C + (long long)row * N + colb;
#pragma unroll
                for (int c4 = 0; c4 < 8; c4++) {
                    float4 bb = *(const float4*)(bias + colb + (c4 << 2));
                    if (flags & F_BIAS2) {
                        float4 b2v = *(const float4*)(bias2 + colb + (c4 << 2));
                        bb.x += b2v.x; bb.y += b2v.y; bb.z += b2v.z; bb.w += b2v.w;
                    }
                    float4 v;
                    v.x = __uint_as_float(r[c4 * 4 + 0]) + bb.x;
                    v.y = __uint_as_float(r[c4 * 4 + 1]) + bb.y;
                    v.z = __uint_as_float(r[c4 * 4 + 2]) + bb.z;
                    v.w = __uint_as_float(r[c4 * 4 + 3]) + bb.w;
                    if (flags & F_RELU) {
                        v.x = fmaxf(v.x, 0.f); v.y = fmaxf(v.y, 0.f);
                        v.z = fmaxf(v.z, 0.f); v.w = fmaxf(v.w, 0.f);
                    }
                    *(float4*)(cp + (c4 << 2)) = v;
                }
            }
        }
        TC_FENCE_BEFORE();
    }
    __syncthreads();
    if (warp == 0) TC_DEALLOC(tmem, 256);

#else
    // =========== correctness-only fallback (runs only without the 103a cubin) ===========
    float* As = (float*)dsm;                 // [128][33]
    float* Bs = (float*)dsm + 128 * 33;      // [32][257]

    float acc[64];
#pragma unroll
    for (int i = 0; i < 64; i++) acc[i] = 0.f;

    for (int kt = 0; kt < nkt; kt++) {
        const float* Ax; const float* Bx; int kk;
        if (kt < nk1) { Ax = A1; Bx = B1; kk = kt; }
        else          { Ax = A2; Bx = B2; kk = kt - nk1; }
#pragma unroll
        for (int i = 0; i < 8; i++) {
            int idx = tid + (i << 9);
            int row = idx >> 5, k = idx & 31;
            int gr = bm + row;
            As[row * 33 + k] = (gr < M) ? Ax[(long long)gr * K + (kk << 5) + k] : 0.f;
        }
#pragma unroll
        for (int i = 0; i < 16; i++) {
            int idx = tid + (i << 9);
            int k = idx >> 8, n = idx & 255;
            Bs[k * 257 + n] = Bx[(long long)((kk << 5) + k) * N + bn + n];
        }
        __syncthreads();
        for (int k = 0; k < 32; k++) {
#pragma unroll
            for (int i = 0; i < 64; i++) {
                int o = tid + (i << 9);
                int row = o >> 8, col = o & 255;
                acc[i] = fmaf(As[row * 33 + k], Bs[k * 257 + col], acc[i]);
            }
        }
        __syncthreads();
    }
#pragma unroll
    for (int i = 0; i < 64; i++) {
        int o = tid + (i << 9);
        int row = o >> 8, col = o & 255;
        int gr = bm + row;
        if (gr >= M) continue;
        float v = acc[i] + bias[bn + col];
        if (flags & F_BIAS2) v += bias2[bn + col];
        if (flags & F_RELU)  v = fmaxf(v, 0.f);
        C[(long long)gr * N + bn + col] = v;
    }
#endif
}

// ---------------- CSR build: count -> scan -> fill ----------------
__global__ void count_kernel(const int* __restrict__ edges, int* __restrict__ cnt)
{
    int idx = blockIdx.x * blockDim.x + threadIdx.x;
    if (idx >= TEDGE * NEDGE) return;
    int t = idx / NEDGE;
    int e = idx - t * NEDGE;
    int dn = __ldg(edges + (long long)t * 2 * NEDGE + NEDGE + e);
    atomicAdd(&cnt[t * NNODES + dn], 1);
}

__global__ void scan_kernel(const int* __restrict__ cnt, int* __restrict__ indptr,
                            int* __restrict__ fill)
{
    __shared__ int sh[1024];
    __shared__ int run;
    int t = blockIdx.x;
    if (threadIdx.x == 0) { run = 0; indptr[t * (NNODES + 1)] = 0; }
    __syncthreads();
    const int* c = cnt + t * NNODES;
    int* ip = indptr + t * (NNODES + 1);
    for (int base = 0; base < NNODES; base += 1024) {
        int i = base + threadIdx.x;
        int v = (i < NNODES) ? c[i] : 0;
        sh[threadIdx.x] = v;
        __syncthreads();
        for (int off = 1; off < 1024; off <<= 1) {
            int x = (threadIdx.x >= off) ? sh[threadIdx.x - off] : 0;
            __syncthreads();
            sh[threadIdx.x] += x;
            __syncthreads();
        }
        if (i < NNODES) ip[i + 1] = run + sh[threadIdx.x];
        __syncthreads();
        if (threadIdx.x == 0) run += sh[1023];
        __syncthreads();
    }
    for (int i = threadIdx.x; i < NNODES; i += 1024)
        fill[t * NNODES + i] = ip[i];
}

__global__ void fill_kernel(const int* __restrict__ edges, int* __restrict__ fill,
                            int* __restrict__ esrc)
{
    int idx = blockIdx.x * blockDim.x + threadIdx.x;
    if (idx >= TEDGE * NEDGE) return;
    int t = idx / NEDGE;
    int e = idx - t * NEDGE;
    const int* base = edges + (long long)t * 2 * NEDGE;
    int sn = __ldg(base + e);
    int dn = __ldg(base + NEDGE + e);
    int pos = atomicAdd(&fill[t * NNODES + dn], 1);
    esrc[t * NEDGE + pos] = sn;
}

// ---------------- gather: 4 warps per (t,node); each warp owns 128 features ----
__global__ void gather_kernel(const float* __restrict__ h, float* __restrict__ agg6,
                              const int* __restrict__ indptr, const int* __restrict__ esrc)
{
    int gw   = (blockIdx.x * blockDim.x + threadIdx.x) >> 5;
    int lane = threadIdx.x & 31;
    if (gw >= TEDGE * NNODES * 4) return;
    int part = gw & 3;
    int seg  = gw >> 2;
    int t = seg / NNODES;
    int node = seg - t * NNODES;
    int beg = __ldg(indptr + t * (NNODES + 1) + node);
    int end = __ldg(indptr + t * (NNODES + 1) + node + 1);
    int col = (part << 5) + lane;   // float4 index 0..127

    const float4* drow = (const float4*)(h + ((long long)c_dstT[t] * NNODES + node) * HDIM);
    float4 a = __ldg(drow + col);

    const float* hsrc = h + (long long)c_srcT[t] * NNODES * HDIM;
    const int* el = esrc + (long long)t * NEDGE;

    int j = beg;
    for (; j + 3 < end; j += 4) {
        int s0 = __ldg(el + j), s1 = __ldg(el + j + 1);
        int s2 = __ldg(el + j + 2), s3 = __ldg(el + j + 3);
        float4 p0 = __ldg((const float4*)(hsrc + (long long)s0 * HDIM) + col);
        float4 p1 = __ldg((const float4*)(hsrc + (long long)s1 * HDIM) + col);
        float4 p2 = __ldg((const float4*)(hsrc + (long long)s2 * HDIM) + col);
        float4 p3 = __ldg((const float4*)(hsrc + (long long)s3 * HDIM) + col);
        a.x += (p0.x + p1.x) + (p2.x + p3.x);
        a.y += (p0.y + p1.y) + (p2.y + p3.y);
        a.z += (p0.z + p1.z) + (p2.z + p3.z);
        a.w += (p0.w + p1.w) + (p2.w + p3.w);
    }
    for (; j < end; j++) {
        int s0 = __ldg(el + j);
        float4 p0 = __ldg((const float4*)(hsrc + (long long)s0 * HDIM) + col);
        a.x += p0.x; a.y += p0.y; a.z += p0.z; a.w += p0.w;
    }

    ((float4*)(agg6 + ((long long)t * NNODES + node) * HDIM))[col] = a;
}

// ---------------- output head ----------------
__global__ void head_kernel(const float* __restrict__ h0, const float* __restrict__ Wout,
                            const float* __restrict__ bout, float* __restrict__ out)
{
    int node = (blockIdx.x * blockDim.x + threadIdx.x) >> 5;
    int lane = threadIdx.x & 31;
    if (node >= NNODES) return;
    const float4* row = (const float4*)(h0 + (long long)node * HDIM);
    const float4* w4  = (const float4*)Wout;
    float s = 0.f;
#pragma unroll
    for (int k = 0; k < 4; k++) {
        float4 a = row[lane + (k << 5)];
        float4 w = __ldg(w4 + lane + (k << 5));
        s += a.x * w.x + a.y * w.y + a.z * w.z + a.w * w.w;
    }
#pragma unroll
    for (int off = 16; off; off >>= 1) s += __shfl_down_sync(0xffffffffu, s, off);
    if (lane == 0) out[node] = s + bout[0];
}

// ---------------- host launch ----------------
extern "C" void kernel_launch(void* const* d_in, const int* in_sizes, int n_in,
                              void* d_out, int out_size)
{
    const float *x = nullptr, *Win = nullptr, *bin = nullptr;
    const float *W1 = nullptr, *b1 = nullptr, *W2 = nullptr, *b2 = nullptr;
    const float *Wout = nullptr, *bout = nullptr;
    const int* edges = nullptr;

    for (int i = 0; i < n_in; i++) {
        int s = in_sizes[i];
        const void* p = d_in[i];
        switch (s) {
            case 6400000: x    = (const float*)p; break;
            case 163840:  Win  = (const float*)p; break;
            case 2560:    bin  = (const float*)p; break;
            case 3145728: if (!W1) W1 = (const float*)p; else W2 = (const float*)p; break;
            case 6144:    if (!b1) b1 = (const float*)p; else b2 = (const float*)p; break;
            case 512:     Wout = (const float*)p; break;
            case 1:       bout = (const float*)p; break;
            case 1920000: edges = (const int*)p; break;
        }
    }

    static bool attr_done = false;
    if (!attr_done) {
        cudaFuncSetAttribute(gemm_kernel,
                             cudaFuncAttributeMaxDynamicSharedMemorySize, SMEM_BYTES);
        attr_done = true;
    }

    float *hA, *hB, *agg6, *tmp6;
    int *cnt, *fillp, *indptr, *esrc;
    cudaGetSymbolAddress((void**)&hA,     g_hA);
    cudaGetSymbolAddress((void**)&hB,     g_hB);
    cudaGetSymbolAddress((void**)&agg6,   g_agg6);
    cudaGetSymbolAddress((void**)&tmp6,   g_tmp6);
    cudaGetSymbolAddress((void**)&cnt,    g_cnt);
    cudaGetSymbolAddress((void**)&fillp,  g_fill);
    cudaGetSymbolAddress((void**)&indptr, g_indptr);
    cudaGetSymbolAddress((void**)&esrc,   g_esrc);

    const int gy = (NNODES + 127) / 128;   // 157
    const int dstT[TEDGE] = {1, 0, 2, 3, 0, 4};

    // 0) CSR build (edge structure is layer-independent)
    cudaMemsetAsync(cnt, 0, (size_t)TEDGE * NNODES * sizeof(int));
    count_kernel<<<(TEDGE * NEDGE + 255) / 256, 256>>>(edges, cnt);
    scan_kernel<<<TEDGE, 1024>>>(cnt, indptr, fillp);
    fill_kernel<<<(TEDGE * NEDGE + 255) / 256, 256>>>(edges, fillp, esrc);

    // 1) input projection: h = relu(x @ W_in + b_in), batched over 5 types (K=64)
    {
        GemmMap m = {};
        for (int t = 0; t < NTYPES; t++) {
            m.aoff[t]    = (long long)t * NNODES * FIN;
            m.boff[t]    = (long long)t * FIN * HDIM;
            m.biasoff[t] = (long long)t * HDIM;
            m.coff[t]    = (long long)t * NH;
            m.flags[t]   = F_RELU;
        }
        gemm_kernel<<<dim3(2, gy, NTYPES), 512, SMEM_BYTES>>>(
            x, Win, bin, hA, NNODES, HDIM, FIN, m);
    }

    float* hcur = hA;
    float* hnext = hB;

    for (int l = 0; l < 2; l++) {
        // 2a+2b) fused gather: agg6[t] = h[dstT[t]] + segment_sum(h[srcT[t]])
        {
            int warps = TEDGE * NNODES * 4;           // 480000
            int blocks = (warps + 7) / 8;
            gather_kernel<<<blocks, 256>>>(hcur, agg6, indptr, esrc);
        }
        // 2c) GEMM1: tmp6[t] = relu(agg6[t] @ W1[l,t] + b1[l,t])
        {
            GemmMap m = {};
            for (int t = 0; t < TEDGE; t++) {
                m.aoff[t]    = (long long)t * NH;
                m.boff[t]    = ((long long)l * TEDGE + t) * HDIM * HDIM;
                m.biasoff[t] = ((long long)l * TEDGE + t) * HDIM;
                m.coff[t]    = (long long)t * NH;
                m.flags[t]   = F_RELU;
            }
            gemm_kernel<<<dim3(2, gy, TEDGE), 512, SMEM_BYTES>>>(
                agg6, W1, b1, tmp6, NNODES, HDIM, HDIM, m);
        }
        // 2d) GEMM2 merged: one launch, 5 dst planes.
        //     z1 fuses t=1 and t=4 (both dst 0) via K-concatenation + bias2.
        {
            GemmMap m = {};
            const int zs[5] = {0, 1, 2, 3, 5};
            for (int zi = 0; zi < 5; zi++) {
                int t = zs[zi];
                m.aoff[zi]    = (long long)t * NH;
                m.boff[zi]    = ((long long)l * TEDGE + t) * HDIM * HDIM;
                m.biasoff[zi] = ((long long)l * TEDGE + t) * HDIM;
                m.coff[zi]    = (long long)dstT[t] * NH;
                m.flags[zi]   = F_RELU;
                m.nk2[zi]     = 0;
            }
            // z index 1 corresponds to t=1 -> add segment 2 for t=4
            m.aoff2[1]    = (long long)4 * NH;
            m.boff2[1]    = ((long long)l * TEDGE + 4) * HDIM * HDIM;
            m.biasoff2[1] = ((long long)l * TEDGE + 4) * HDIM;
            m.nk2[1]      = HDIM / 32;            // 16 extra k-tiles
            m.flags[1]    = F_RELU | F_BIAS2;
            gemm_kernel<<<dim3(2, gy, 5), 512, SMEM_BYTES>>>(
                tmp6, W2, b2, hnext, NNODES, HDIM, HDIM, m);
        }
        float* tswap = hcur; hcur = hnext; hnext = tswap;
    }

    // 3) output head on type 0
    {
        int blocks = (NNODES + 7) / 8;
        head_kernel<<<blocks, 256>>>(hcur, Wout, bout, (float*)d_out);
    }
    (void)out_size; (void)n_in;
}

// round 14
// speedup vs baseline: 3.3560x; 1.0102x over previous
#include <cuda_runtime.h>
#include <cstdint>

// ---------------- problem constants ----------------
#define NNODES 20000
#define FIN    64
#define HDIM   512
#define NTYPES 5
#define TEDGE  6
#define NEDGE  160000
#define NH     (NNODES * HDIM)

// EDGE_TYPES = ((4,1),(1,0),(0,2),(2,3),(3,0),(1,4))
__constant__ int c_srcT[TEDGE] = {4, 1, 0, 2, 3, 1};
__constant__ int c_dstT[TEDGE] = {1, 0, 2, 3, 0, 4};

// ---------------- device scratch (no allocs allowed) ----------------
__device__ float g_hA[NTYPES * NH];
__device__ float g_hB[NTYPES * NH];
__device__ float g_agg6[TEDGE * NH];
__device__ float g_tmp6[TEDGE * NH];
__device__ int   g_cnt[TEDGE * NNODES];
__device__ int   g_fill[TEDGE * NNODES];
__device__ int   g_indptr[TEDGE * (NNODES + 1)];
__device__ int   g_esrc[TEDGE * NEDGE];

#define F_RELU  1
#define F_BIAS2 2

// Per-z GEMM description. Optional second K segment (aoff2/boff2, nk2 k-tiles)
// concatenates onto K: D = A1@B1 + A2@B2 (+bias (+bias2)).
struct GemmMap {
    long long aoff[TEDGE],  aoff2[TEDGE];
    long long boff[TEDGE],  boff2[TEDGE];
    long long biasoff[TEDGE], biasoff2[TEDGE];
    long long coff[TEDGE];
    int       nk2[TEDGE];
    int       flags[TEDGE];
};

// Arch-feature gate: tcgen05 only exists in the compute_103a / compute_100a passes.
#if defined(__CUDA_ARCH__) && (defined(__CUDA_ARCH_FEAT_SM103_ALL) || defined(__CUDA_ARCH_FEAT_SM100_ALL))
#define USE_TCGEN05 1
#else
#define USE_TCGEN05 0
#endif

__device__ __forceinline__ void splitf(float f, uint32_t& hi, uint32_t& lo) {
    uint32_t h = __float_as_uint(f) & 0xFFFFE000u;   // exact tf32 value
    hi = h;
    lo = __float_as_uint(f - __uint_as_float(h));    // exact residual
}

// smem planes within one buffer: A (128x32) hi/lo = 16KB each, B (256x32) hi/lo = 32KB each
#define P_AH 0
#define P_AL 16384
#define P_BH 32768
#define P_BL 65536
#define BUF_BYTES 98304
#define SMEM_BYTES (2 * BUF_BYTES + 2048)   // 198,656 B

#if USE_TCGEN05
// ---------------- tcgen05 helpers (compiled only for *a* targets) ----------------
__device__ __forceinline__ uint32_t smem_u32ptr(const void* p) {
    uint32_t a;
    asm("{ .reg .u64 t; cvta.to.shared.u64 t, %1; cvt.u32.u64 %0, t; }" : "=r"(a) : "l"(p));
    return a;
}
__device__ __forceinline__ uint32_t elect1() {
    uint32_t r;
    asm volatile("{ .reg .pred p; elect.sync _|p, 0xFFFFFFFF; selp.b32 %0,1,0,p; }" : "=r"(r));
    return r;
}
__device__ __forceinline__ void mbar_init(uint32_t a, uint32_t c) {
    asm volatile("mbarrier.init.shared.b64 [%0], %1;" :: "r"(a), "r"(c) : "memory");
}
__device__ __forceinline__ void mbar_wait(uint32_t a, uint32_t ph) {
    asm volatile(
        "{ .reg .pred P;\n"
        "WL%=: mbarrier.try_wait.parity.acquire.cta.shared::cta.b64 P, [%0], %1, 0x989680;\n"
        "@P bra WD%=;\n"
        "bra WL%=;\n"
        "WD%=: }"
        :: "r"(a), "r"(ph) : "memory");
}
#define TC_ALLOC(slot, n) \
    asm volatile("tcgen05.alloc.cta_group::1.sync.aligned.shared::cta.b32 [%0], %1;" \
                 :: "r"(slot), "r"((uint32_t)(n)) : "memory")
#define TC_RELQ() \
    asm volatile("tcgen05.relinquish_alloc_permit.cta_group::1.sync.aligned;")
#define TC_DEALLOC(t, n) \
    asm volatile("tcgen05.dealloc.cta_group::1.sync.aligned.b32 %0, %1;" :: "r"(t), "r"((uint32_t)(n)))
#define TC_COMMIT(mb) \
    asm volatile("tcgen05.commit.cta_group::1.mbarrier::arrive::one.shared::cluster.b64 [%0];" \
                 :: "r"(mb) : "memory")
#define TC_FENCE_AFTER()  asm volatile("tcgen05.fence::after_thread_sync;" ::: "memory")
#define TC_FENCE_BEFORE() asm volatile("tcgen05.fence::before_thread_sync;" ::: "memory")
#define TC_WAIT_LD()      asm volatile("tcgen05.wait::ld.sync.aligned;" ::: "memory")
#define FENCE_PROXY()     asm volatile("fence.proxy.async.shared::cta;" ::: "memory")
#define SMEM_SWZ(off) ((off) ^ (((off) >> 3) & 0x70))

static __device__ __forceinline__ uint64_t make_desc(uint32_t addr) {
    const uint64_t base =
        (uint64_t(2) << 61) | (uint64_t(1) << 46) | (uint64_t(64) << 32) | (uint64_t(1) << 16);
    return base | ((uint64_t)(addr >> 4) & 0x3FFF);
}
// idesc: dtype=F32(1 @ [4:5]), atype=btype=TF32(2), N=128 (N/8 @ [17:22]), M=128 (M/16 @ [24:28])
#define TC_IDESC ((1u << 4) | (2u << 7) | (2u << 10) | ((128u / 8u) << 17) | ((128u / 16u) << 24))

__device__ __forceinline__ void tc_mma_tf32(uint32_t d, uint64_t a, uint64_t b, uint32_t en) {
    asm volatile(
        "{\n\t"
        ".reg .pred p;\n\t"
        "setp.ne.u32 p, %4, 0;\n\t"
        "tcgen05.mma.cta_group::1.kind::tf32 [%0], %1, %2, %3, {%5,%5,%5,%5}, p;\n\t"
        "}"
        :: "r"(d), "l"(a), "l"(b), "r"(TC_IDESC), "r"(en), "r"(0u)
        : "memory");
}
#endif  // USE_TCGEN05

// ---------------- batched GEMM: C[z](M x 512) block = 128 x 256 per CTA ----------------
__global__ __launch_bounds__(512, 1)
void gemm_kernel(const float* __restrict__ Ab, const float* __restrict__ Bb,
                 const float* __restrict__ biasb, float* __restrict__ Cb,
                 int M, int N, int K, GemmMap map)
{
    extern __shared__ uint32_t dsm[];

    const int z = blockIdx.z;
    const float* __restrict__ A1    = Ab + map.aoff[z];
    const float* __restrict__ A2    = Ab + map.aoff2[z];
    const float* __restrict__ B1    = Bb + map.boff[z];
    const float* __restrict__ B2    = Bb + map.boff2[z];
    const float* __restrict__ bias  = biasb + map.biasoff[z];
    const float* __restrict__ bias2 = biasb + map.biasoff2[z];
    float* __restrict__       C     = Cb + map.coff[z];
    const int flags = map.flags[z];
    const int nk1 = K >> 5;
    const int nkt = nk1 + map.nk2[z];

    const int tid  = threadIdx.x;
    const int warp = tid >> 5;
    const int lane = tid & 31;
    const int bm = blockIdx.y << 7;
    const int bn = blockIdx.x << 8;      // 256-wide N block

#if USE_TCGEN05
    uint32_t sbase = smem_u32ptr(dsm);
    uint32_t tslot = sbase;
    uint32_t mb0 = sbase + 8, mb1 = sbase + 16;
    uint32_t abase = (sbase + 1023) & ~1023u;
    char* smc = (char*)dsm + (abase - sbase);

    if (tid == 0) { mbar_init(mb0, 1); mbar_init(mb1, 1); }
    if (warp == 0) { TC_ALLOC(tslot, 256); TC_RELQ(); }
    __syncthreads();
    uint32_t tmem;
    asm volatile("ld.shared.b32 %0, [%1];" : "=r"(tmem) : "r"(tslot));

    int ph0 = 0, ph1 = 0;

    for (int kt = 0; kt < nkt; kt++) {
        const int b = kt & 1;
        const uint32_t bufb = abase + b * BUF_BYTES;
        char* bufc = smc + b * BUF_BYTES;
        if (kt >= 2) {
            if (b == 0) { mbar_wait(mb0, ph0); ph0 ^= 1; }
            else        { mbar_wait(mb1, ph1); ph1 ^= 1; }
        }

        const float* Ax; const float* Bx; int kk;
        if (kt < nk1) { Ax = A1; Bx = B1; kk = kt; }
        else          { Ax = A2; Bx = B2; kk = kt - nk1; }

        // A tile: [m 0..127][k 0..31], K-major 128B rows, SW128
#pragma unroll
        for (int i = 0; i < 2; i++) {
            int id = tid + (i << 9);
            int row = id >> 3, q = id & 7;
            int gr = bm + row;
            float4 v = make_float4(0.f, 0.f, 0.f, 0.f);
            if (gr < M) v = *(const float4*)(Ax + (long long)gr * K + (kk << 5) + (q << 2));
            uint4 h, l;
            splitf(v.x, h.x, l.x); splitf(v.y, h.y, l.y);
            splitf(v.z, h.z, l.z); splitf(v.w, h.w, l.w);
            uint32_t sw = SMEM_SWZ((row << 7) + (q << 4));
            *(uint4*)(bufc + P_AH + sw) = h;
            *(uint4*)(bufc + P_AL + sw) = l;
        }
        // B tile: rows = n (256), cols = k (32); transpose from [K,N]
#pragma unroll
        for (int i = 0; i < 4; i++) {
            int id = tid + (i << 9);
            int n = id & 255, q = id >> 8;
            const float* bp = Bx + (long long)((kk << 5) + (q << 2)) * N + bn + n;
            float v0 = __ldg(bp);
            float v1 = __ldg(bp + N);
            float v2 = __ldg(bp + 2 * N);
            float v3 = __ldg(bp + 3 * N);
            uint4 h, l;
            splitf(v0, h.x, l.x); splitf(v1, h.y, l.y);
            splitf(v2, h.z, l.z); splitf(v3, h.w, l.w);
            uint32_t sw = SMEM_SWZ((n << 7) + (q << 4));
            *(uint4*)(bufc + P_BH + sw) = h;
            *(uint4*)(bufc + P_BL + sw) = l;
        }
        FENCE_PROXY();
        __syncthreads();

        if (warp == 0) {
            if (elect1()) {
                uint64_t dah  = make_desc(bufb + P_AH);
                uint64_t dal  = make_desc(bufb + P_AL);
                uint64_t dbh0 = make_desc(bufb + P_BH);
                uint64_t dbh1 = make_desc(bufb + P_BH + 16384);
                uint64_t dbl0 = make_desc(bufb + P_BL);
                uint64_t dbl1 = make_desc(bufb + P_BL + 16384);
#pragma unroll
                for (int ks = 0; ks < 4; ks++) {
                    uint64_t o = (uint64_t)(ks * 2);
                    uint32_t en0 = (kt == 0 && ks == 0) ? 0u : 1u;
                    // N half 0 -> D cols 0..127
                    tc_mma_tf32(tmem,       dah + o, dbh0 + o, en0);
                    tc_mma_tf32(tmem,       dah + o, dbl0 + o, 1u);
                    tc_mma_tf32(tmem,       dal + o, dbh0 + o, 1u);
                    // N half 1 -> D cols 128..255
                    tc_mma_tf32(tmem + 128, dah + o, dbh1 + o, en0);
                    tc_mma_tf32(tmem + 128, dah + o, dbl1 + o, 1u);
                    tc_mma_tf32(tmem + 128, dal + o, dbh1 + o, 1u);
                }
                TC_COMMIT(b ? mb1 : mb0);
            }
        }
    }

    {
        int lb = (nkt - 1) & 1;
        mbar_wait(lb ? mb1 : mb0, lb ? ph1 : ph0);
    }
    TC_FENCE_AFTER();

    // epilogue: warp w -> rows (w&3)*32 (its subpartition), cols (w>>2)*32 of each half
    {
        int wc = warp >> 2;
        int row = bm + ((warp & 3) << 5) + lane;
#pragma unroll
        for (int half = 0; half < 2; half++) {
            uint32_t r[32];
            asm volatile(
                "tcgen05.ld.sync.aligned.32x32b.x32.b32 "
                "{%0, %1, %2, %3, %4, %5, %6, %7, "
                " %8, %9, %10, %11, %12, %13, %14, %15, "
                " %16, %17, %18, %19, %20, %21, %22, %23, "
                " %24, %25, %26, %27, %28, %29, %30, %31}, [%32];"
                : "=r"(r[0]),  "=r"(r[1]),  "=r"(r[2]),  "=r"(r[3]),
                  "=r"(r[4]),  "=r"(r[5]),  "=r"(r[6]),  "=r"(r[7]),
                  "=r"(r[8]),  "=r"(r[9]),  "=r"(r[10]), "=r"(r[11]),
                  "=r"(r[12]), "=r"(r[13]), "=r"(r[14]), "=r"(r[15]),
                  "=r"(r[16]), "=r"(r[17]), "=r"(r[18]), "=r"(r[19]),
                  "=r"(r[20]), "=r"(r[21]), "=r"(r[22]), "=r"(r[23]),
                  "=r"(r[24]), "=r"(r[25]), "=r"(r[26]), "=r"(r[27]),
                  "=r"(r[28]), "=r"(r[29]), "=r"(r[30]), "=r"(r[31])
                : "r"(tmem + (half << 7) + (wc << 5)));
            TC_WAIT_LD();

            if (row < M) {
                int colb = bn + (half << 7) + (wc << 5);
                float* cp = C + (long long)row * N + colb;
#pragma unroll
                for (int c4 = 0; c4 < 8; c4++) {
                    float4 bb = *(const float4*)(bias + colb + (c4 << 2));
                    if (flags & F_BIAS2) {
                        float4 b2v = *(const float4*)(bias2 + colb + (c4 << 2));
                        bb.x += b2v.x; bb.y += b2v.y; bb.z += b2v.z; bb.w += b2v.w;
                    }
                    float4 v;
                    v.x = __uint_as_float(r[c4 * 4 + 0]) + bb.x;
                    v.y = __uint_as_float(r[c4 * 4 + 1]) + bb.y;
                    v.z = __uint_as_float(r[c4 * 4 + 2]) + bb.z;
                    v.w = __uint_as_float(r[c4 * 4 + 3]) + bb.w;
                    if (flags & F_RELU) {
                        v.x = fmaxf(v.x, 0.f); v.y = fmaxf(v.y, 0.f);
                        v.z = fmaxf(v.z, 0.f); v.w = fmaxf(v.w, 0.f);
                    }
                    *(float4*)(cp + (c4 << 2)) = v;
                }
            }
        }
        TC_FENCE_BEFORE();
    }
    __syncthreads();
    if (warp == 0) TC_DEALLOC(tmem, 256);

#else
    // =========== correctness-only fallback (runs only without the 103a cubin) ===========
    float* As = (float*)dsm;                 // [128][33]
    float* Bs = (float*)dsm + 128 * 33;      // [32][257]

    float acc[64];
#pragma unroll
    for (int i = 0; i < 64; i++) acc[i] = 0.f;

    for (int kt = 0; kt < nkt; kt++) {
        const float* Ax; const float* Bx; int kk;
        if (kt < nk1) { Ax = A1; Bx = B1; kk = kt; }
        else          { Ax = A2; Bx = B2; kk = kt - nk1; }
#pragma unroll
        for (int i = 0; i < 8; i++) {
            int idx = tid + (i << 9);
            int row = idx >> 5, k = idx & 31;
            int gr = bm + row;
            As[row * 33 + k] = (gr < M) ? Ax[(long long)gr * K + (kk << 5) + k] : 0.f;
        }
#pragma unroll
        for (int i = 0; i < 16; i++) {
            int idx = tid + (i << 9);
            int k = idx >> 8, n = idx & 255;
            Bs[k * 257 + n] = Bx[(long long)((kk << 5) + k) * N + bn + n];
        }
        __syncthreads();
        for (int k = 0; k < 32; k++) {
#pragma unroll
            for (int i = 0; i < 64; i++) {
                int o = tid + (i << 9);
                int row = o >> 8, col = o & 255;
                acc[i] = fmaf(As[row * 33 + k], Bs[k * 257 + col], acc[i]);
            }
        }
        __syncthreads();
    }
#pragma unroll
    for (int i = 0; i < 64; i++) {
        int o = tid + (i << 9);
        int row = o >> 8, col = o & 255;
        int gr = bm + row;
        if (gr >= M) continue;
        float v = acc[i] + bias[bn + col];
        if (flags & F_BIAS2) v += bias2[bn + col];
        if (flags & F_RELU)  v = fmaxf(v, 0.f);
        C[(long long)gr * N + bn + col] = v;
    }
#endif
}

// ---------------- CSR build: count -> scan -> fill ----------------
__global__ void count_kernel(const int* __restrict__ edges, int* __restrict__ cnt)
{
    int idx = blockIdx.x * blockDim.x + threadIdx.x;
    if (idx >= TEDGE * NEDGE) return;
    int t = idx / NEDGE;
    int e = idx - t * NEDGE;
    int dn = __ldg(edges + (long long)t * 2 * NEDGE + NEDGE + e);
    atomicAdd(&cnt[t * NNODES + dn], 1);
}

__global__ void scan_kernel(const int* __restrict__ cnt, int* __restrict__ indptr,
                            int* __restrict__ fill)
{
    __shared__ int sh[1024];
    __shared__ int run;
    int t = blockIdx.x;
    if (threadIdx.x == 0) { run = 0; indptr[t * (NNODES + 1)] = 0; }
    __syncthreads();
    const int* c = cnt + t * NNODES;
    int* ip = indptr + t * (NNODES + 1);
    for (int base = 0; base < NNODES; base += 1024) {
        int i = base + threadIdx.x;
        int v = (i < NNODES) ? c[i] : 0;
        sh[threadIdx.x] = v;
        __syncthreads();
        for (int off = 1; off < 1024; off <<= 1) {
            int x = (threadIdx.x >= off) ? sh[threadIdx.x - off] : 0;
            __syncthreads();
            sh[threadIdx.x] += x;
            __syncthreads();
        }
        if (i < NNODES) ip[i + 1] = run + sh[threadIdx.x];
        __syncthreads();
        if (threadIdx.x == 0) run += sh[1023];
        __syncthreads();
    }
    for (int i = threadIdx.x; i < NNODES; i += 1024)
        fill[t * NNODES + i] = ip[i];
}

__global__ void fill_kernel(const int* __restrict__ edges, int* __restrict__ fill,
                            int* __restrict__ esrc)
{
    int idx = blockIdx.x * blockDim.x + threadIdx.x;
    if (idx >= TEDGE * NEDGE) return;
    int t = idx / NEDGE;
    int e = idx - t * NEDGE;
    const int* base = edges + (long long)t * 2 * NEDGE;
    int sn = __ldg(base + e);
    int dn = __ldg(base + NEDGE + e);
    int pos = atomicAdd(&fill[t * NNODES + dn], 1);
    esrc[t * NEDGE + pos] = sn;
}

// ---------------- gather: 4 warps per (t,node); each warp owns 128 features ----
__global__ void gather_kernel(const float* __restrict__ h, float* __restrict__ agg6,
                              const int* __restrict__ indptr, const int* __restrict__ esrc)
{
    int gw   = (blockIdx.x * blockDim.x + threadIdx.x) >> 5;
    int lane = threadIdx.x & 31;
    if (gw >= TEDGE * NNODES * 4) return;
    int part = gw & 3;
    int seg  = gw >> 2;
    int t = seg / NNODES;
    int node = seg - t * NNODES;
    int beg = __ldg(indptr + t * (NNODES + 1) + node);
    int end = __ldg(indptr + t * (NNODES + 1) + node + 1);
    int col = (part << 5) + lane;   // float4 index 0..127

    const float4* drow = (const float4*)(h + ((long long)c_dstT[t] * NNODES + node) * HDIM);
    float4 a = __ldg(drow + col);

    const float* hsrc = h + (long long)c_srcT[t] * NNODES * HDIM;
    const int* el = esrc + (long long)t * NEDGE;

    int j = beg;
    for (; j + 3 < end; j += 4) {
        int s0 = __ldg(el + j), s1 = __ldg(el + j + 1);
        int s2 = __ldg(el + j + 2), s3 = __ldg(el + j + 3);
        float4 p0 = __ldg((const float4*)(hsrc + (long long)s0 * HDIM) + col);
        float4 p1 = __ldg((const float4*)(hsrc + (long long)s1 * HDIM) + col);
        float4 p2 = __ldg((const float4*)(hsrc + (long long)s2 * HDIM) + col);
        float4 p3 = __ldg((const float4*)(hsrc + (long long)s3 * HDIM) + col);
        a.x += (p0.x + p1.x) + (p2.x + p3.x);
        a.y += (p0.y + p1.y) + (p2.y + p3.y);
        a.z += (p0.z + p1.z) + (p2.z + p3.z);
        a.w += (p0.w + p1.w) + (p2.w + p3.w);
    }
    for (; j < end; j++) {
        int s0 = __ldg(el + j);
        float4 p0 = __ldg((const float4*)(hsrc + (long long)s0 * HDIM) + col);
        a.x += p0.x; a.y += p0.y; a.z += p0.z; a.w += p0.w;
    }

    ((float4*)(agg6 + ((long long)t * NNODES + node) * HDIM))[col] = a;
}

// ---------------- output head ----------------
__global__ void head_kernel(const float* __restrict__ h0, const float* __restrict__ Wout,
                            const float* __restrict__ bout, float* __restrict__ out)
{
    int node = (blockIdx.x * blockDim.x + threadIdx.x) >> 5;
    int lane = threadIdx.x & 31;
    if (node >= NNODES) return;
    const float4* row = (const float4*)(h0 + (long long)node * HDIM);
    const float4* w4  = (const float4*)Wout;
    float s = 0.f;
#pragma unroll
    for (int k = 0; k < 4; k++) {
        float4 a = row[lane + (k << 5)];
        float4 w = __ldg(w4 + lane + (k << 5));
        s += a.x * w.x + a.y * w.y + a.z * w.z + a.w * w.w;
    }
#pragma unroll
    for (int off = 16; off; off >>= 1) s += __shfl_down_sync(0xffffffffu, s, off);
    if (lane == 0) out[node] = s + bout[0];
}

// ---------------- host launch ----------------
extern "C" void kernel_launch(void* const* d_in, const int* in_sizes, int n_in,
                              void* d_out, int out_size)
{
    const float *x = nullptr, *Win = nullptr, *bin = nullptr;
    const float *W1 = nullptr, *b1 = nullptr, *W2 = nullptr, *b2 = nullptr;
    const float *Wout = nullptr, *bout = nullptr;
    const int* edges = nullptr;

    for (int i = 0; i < n_in; i++) {
        int s = in_sizes[i];
        const void* p = d_in[i];
        switch (s) {
            case 6400000: x    = (const float*)p; break;
            case 163840:  Win  = (const float*)p; break;
            case 2560:    bin  = (const float*)p; break;
            case 3145728: if (!W1) W1 = (const float*)p; else W2 = (const float*)p; break;
            case 6144:    if (!b1) b1 = (const float*)p; else b2 = (const float*)p; break;
            case 512:     Wout = (const float*)p; break;
            case 1:       bout = (const float*)p; break;
            case 1920000: edges = (const int*)p; break;
        }
    }

    static bool attr_done = false;
    if (!attr_done) {
        cudaFuncSetAttribute(gemm_kernel,
                             cudaFuncAttributeMaxDynamicSharedMemorySize, SMEM_BYTES);
        attr_done = true;
    }

    float *hA, *hB, *agg6, *tmp6;
    int *cnt, *fillp, *indptr, *esrc;
    cudaGetSymbolAddress((void**)&hA,     g_hA);
    cudaGetSymbolAddress((void**)&hB,     g_hB);
    cudaGetSymbolAddress((void**)&agg6,   g_agg6);
    cudaGetSymbolAddress((void**)&tmp6,   g_tmp6);
    cudaGetSymbolAddress((void**)&cnt,    g_cnt);
    cudaGetSymbolAddress((void**)&fillp,  g_fill);
    cudaGetSymbolAddress((void**)&indptr, g_indptr);
    cudaGetSymbolAddress((void**)&esrc,   g_esrc);

    const int gy = (NNODES + 127) / 128;   // 157
    const int dstT[TEDGE] = {1, 0, 2, 3, 0, 4};

    // 0) CSR build (edge structure is layer-independent)
    cudaMemsetAsync(cnt, 0, (size_t)TEDGE * NNODES * sizeof(int));
    count_kernel<<<(TEDGE * NEDGE + 255) / 256, 256>>>(edges, cnt);
    scan_kernel<<<TEDGE, 1024>>>(cnt, indptr, fillp);
    fill_kernel<<<(TEDGE * NEDGE + 255) / 256, 256>>>(edges, fillp, esrc);

    // 1) input projection: h = relu(x @ W_in + b_in), batched over 5 types (K=64)
    {
        GemmMap m = {};
        for (int t = 0; t < NTYPES; t++) {
            m.aoff[t]    = (long long)t * NNODES * FIN;
            m.boff[t]    = (long long)t * FIN * HDIM;
            m.biasoff[t] = (long long)t * HDIM;
            m.coff[t]    = (long long)t * NH;
            m.flags[t]   = F_RELU;
        }
        gemm_kernel<<<dim3(2, gy, NTYPES), 512, SMEM_BYTES>>>(
            x, Win, bin, hA, NNODES, HDIM, FIN, m);
    }

    float* hcur = hA;
    float* hnext = hB;

    for (int l = 0; l < 2; l++) {
        // 2a+2b) fused gather: agg6[t] = h[dstT[t]] + segment_sum(h[srcT[t]])
        {
            int warps = TEDGE * NNODES * 4;           // 480000
            int blocks = (warps + 7) / 8;
            gather_kernel<<<blocks, 256>>>(hcur, agg6, indptr, esrc);
        }
        // 2c) GEMM1: tmp6[t] = relu(agg6[t] @ W1[l,t] + b1[l,t])
        {
            GemmMap m = {};
            for (int t = 0; t < TEDGE; t++) {
                m.aoff[t]    = (long long)t * NH;
                m.boff[t]    = ((long long)l * TEDGE + t) * HDIM * HDIM;
                m.biasoff[t] = ((long long)l * TEDGE + t) * HDIM;
                m.coff[t]    = (long long)t * NH;
                m.flags[t]   = F_RELU;
            }
            gemm_kernel<<<dim3(2, gy, TEDGE), 512, SMEM_BYTES>>>(
                agg6, W1, b1, tmp6, NNODES, HDIM, HDIM, m);
        }
        // 2d) GEMM2 merged: one launch, 5 dst planes.
        //     z1 fuses t=1 and t=4 (both dst 0) via K-concatenation + bias2.
        {
            GemmMap m = {};
            const int zs[5] = {0, 1, 2, 3, 5};
            for (int zi = 0; zi < 5; zi++) {
                int t = zs[zi];
                m.aoff[zi]    = (long long)t * NH;
                m.boff[zi]    = ((long long)l * TEDGE + t) * HDIM * HDIM;
                m.biasoff[zi] = ((long long)l * TEDGE + t) * HDIM;
                m.coff[zi]    = (long long)dstT[t] * NH;
                m.flags[zi]   = F_RELU;
                m.nk2[zi]     = 0;
            }
            // z index 1 corresponds to t=1 -> add segment 2 for t=4
            m.aoff2[1]    = (long long)4 * NH;
            m.boff2[1]    = ((long long)l * TEDGE + 4) * HDIM * HDIM;
            m.biasoff2[1] = ((long long)l * TEDGE + 4) * HDIM;
            m.nk2[1]      = HDIM / 32;            // 16 extra k-tiles
            m.flags[1]    = F_RELU | F_BIAS2;
            gemm_kernel<<<dim3(2, gy, 5), 512, SMEM_BYTES>>>(
                tmp6, W2, b2, hnext, NNODES, HDIM, HDIM, m);
        }
        float* tswap = hcur; hcur = hnext; hnext = tswap;
    }

    // 3) output head on type 0
    {
        int blocks = (NNODES + 7) / 8;
        head_kernel<<<blocks, 256>>>(hcur, Wout, bout, (float*)d_out);
    }
    (void)out_size; (void)n_in;
}